// round 1
// baseline (speedup 1.0000x reference)
#include <cuda_runtime.h>
#include <math.h>

#define LEN 5440
#define NBATCH 2
#define MROWS (NBATCH*LEN)   /* 10880 */
#define DM 256
#define NH 8
#define DFFN 1024
#define NLAYERS 2

#define BM 64
#define BN 64
#define BK 16

__constant__ int c_HW[4] = {64, 32, 16, 8};
__constant__ int c_S[4]  = {0, 4096, 5120, 5376};

// ---------------- scratch (device globals; no allocation) ----------------
__device__ __align__(16) float g_x[MROWS * DM];
__device__ __align__(16) float g_val[MROWS * DM];
__device__ __align__(16) float g_off[MROWS * DM];
__device__ __align__(16) float g_aw[MROWS * NH * 16];
__device__ __align__(16) float g_attn[MROWS * DM];
__device__ __align__(16) float g_tmp[MROWS * DM];
__device__ __align__(16) float g_ffn[MROWS * DFFN];
__device__ __align__(16) float g_ref[MROWS * 8];

// ---------------- copy ----------------
__global__ void copy_kernel(float4* __restrict__ dst, const float4* __restrict__ src, int n4) {
    int i = blockIdx.x * blockDim.x + threadIdx.x;
    if (i < n4) dst[i] = src[i];
}

// ---------------- reference points ----------------
__global__ void refpts_kernel(const float* __restrict__ vr, float* __restrict__ ref) {
    int idx = blockIdx.x * blockDim.x + threadIdx.x;   // n*LEN + t
    if (idx >= MROWS) return;
    int n = idx / LEN, t = idx % LEN;
    int lvl = 3;
    if (t < 4096) lvl = 0; else if (t < 5120) lvl = 1; else if (t < 5376) lvl = 2;
    int s = c_S[lvl], hw = c_HW[lvl];
    int local = t - s;
    int i = local / hw, j = local % hw;
    float ry = (i + 0.5f) / (vr[(n * 4 + lvl) * 2 + 1] * (float)hw);
    float rx = (j + 0.5f) / (vr[(n * 4 + lvl) * 2 + 0] * (float)hw);
#pragma unroll
    for (int l2 = 0; l2 < 4; l2++) {
        ref[idx * 8 + l2 * 2 + 0] = rx * vr[(n * 4 + l2) * 2 + 0];
        ref[idx * 8 + l2 * 2 + 1] = ry * vr[(n * 4 + l2) * 2 + 1];
    }
}

// ---------------- GEMM: C[M,Nc] = (A (+A2)) @ W + bias, optional ReLU ----------------
// Assumes M % BM == 0, Nc % BN == 0, K % BK == 0 (true for all shapes here).
template <bool RELU, bool POSADD>
__global__ void __launch_bounds__(256) gemm_kernel(
    const float* __restrict__ A, const float* __restrict__ A2,
    const float* __restrict__ W, const float* __restrict__ bias,
    float* __restrict__ C, int K, int Nc)
{
    __shared__ __align__(16) float As[BK][BM];
    __shared__ __align__(16) float Ws[BK][BN];
    int tid = threadIdx.x;
    int tx = tid & 15, ty = tid >> 4;
    int rowBase = blockIdx.y * BM;
    int colBase = blockIdx.x * BN;
    float acc[4][4] = {};
    int am = tid >> 2, ac = (tid & 3) * 4;
    int wk = tid >> 4, wn = (tid & 15) * 4;
    for (int k0 = 0; k0 < K; k0 += BK) {
        float4 av = *(const float4*)(A + (size_t)(rowBase + am) * K + k0 + ac);
        if (POSADD) {
            float4 pv = *(const float4*)(A2 + (size_t)(rowBase + am) * K + k0 + ac);
            av.x += pv.x; av.y += pv.y; av.z += pv.z; av.w += pv.w;
        }
        As[ac + 0][am] = av.x;
        As[ac + 1][am] = av.y;
        As[ac + 2][am] = av.z;
        As[ac + 3][am] = av.w;
        *(float4*)&Ws[wk][wn] = *(const float4*)(W + (size_t)(k0 + wk) * Nc + colBase + wn);
        __syncthreads();
#pragma unroll
        for (int kk = 0; kk < BK; kk++) {
            float a0 = As[kk][ty * 4 + 0];
            float a1 = As[kk][ty * 4 + 1];
            float a2 = As[kk][ty * 4 + 2];
            float a3 = As[kk][ty * 4 + 3];
            float4 wv = *(const float4*)&Ws[kk][tx * 4];
            acc[0][0] += a0 * wv.x; acc[0][1] += a0 * wv.y; acc[0][2] += a0 * wv.z; acc[0][3] += a0 * wv.w;
            acc[1][0] += a1 * wv.x; acc[1][1] += a1 * wv.y; acc[1][2] += a1 * wv.z; acc[1][3] += a1 * wv.w;
            acc[2][0] += a2 * wv.x; acc[2][1] += a2 * wv.y; acc[2][2] += a2 * wv.z; acc[2][3] += a2 * wv.w;
            acc[3][0] += a3 * wv.x; acc[3][1] += a3 * wv.y; acc[3][2] += a3 * wv.z; acc[3][3] += a3 * wv.w;
        }
        __syncthreads();
    }
#pragma unroll
    for (int i = 0; i < 4; i++) {
        int row = rowBase + ty * 4 + i;
#pragma unroll
        for (int j = 0; j < 4; j++) {
            int col = colBase + tx * 4 + j;
            float v = acc[i][j] + bias[col];
            if (RELU) v = fmaxf(v, 0.f);
            C[(size_t)row * Nc + col] = v;
        }
    }
}

// ---------------- softmax over groups of 16 ----------------
__global__ void softmax_kernel(float* __restrict__ aw) {
    int g = blockIdx.x * blockDim.x + threadIdx.x;
    if (g >= MROWS * NH) return;
    float* p = aw + (size_t)g * 16;
    float e[16];
    float mx = -1e30f;
#pragma unroll
    for (int i = 0; i < 16; i++) { e[i] = p[i]; mx = fmaxf(mx, e[i]); }
    float s = 0.f;
#pragma unroll
    for (int i = 0; i < 16; i++) { e[i] = expf(e[i] - mx); s += e[i]; }
    float inv = 1.f / s;
#pragma unroll
    for (int i = 0; i < 16; i++) p[i] = e[i] * inv;
}

// ---------------- deformable bilinear sampling ----------------
// One block per (n, t): 8 warps = 8 heads. lane = head-dim channel.
__global__ void __launch_bounds__(256) sample_kernel(
    const float* __restrict__ value, const float* __restrict__ off,
    const float* __restrict__ aw, const float* __restrict__ ref,
    float* __restrict__ attn)
{
    int row = blockIdx.x;              // n*LEN + t
    int h = threadIdx.x >> 5;          // head
    int lane = threadIdx.x & 31;       // head-dim channel
    int n = row / LEN;

    float offv = off[(size_t)row * 256 + h * 32 + lane];                 // 16 (x,y) pairs
    float awv  = (lane < 16) ? aw[(size_t)row * 128 + h * 16 + lane] : 0.f;
    float refv = (lane < 8)  ? ref[(size_t)row * 8 + lane] : 0.f;        // 4 levels x (x,y)

    const float* vbase = value + (size_t)n * LEN * 256 + h * 32 + lane;
    float acc = 0.f;
#pragma unroll
    for (int p = 0; p < 16; p++) {
        int lvl = p >> 2;
        float ox = __shfl_sync(0xffffffffu, offv, 2 * p);
        float oy = __shfl_sync(0xffffffffu, offv, 2 * p + 1);
        float a  = __shfl_sync(0xffffffffu, awv, p);
        float rx = __shfl_sync(0xffffffffu, refv, 2 * lvl);
        float ry = __shfl_sync(0xffffffffu, refv, 2 * lvl + 1);
        int HW = c_HW[lvl], s = c_S[lvl];
        float fw = (float)HW;
        float xf = (rx + ox / fw) * fw - 0.5f;
        float yf = (ry + oy / fw) * fw - 0.5f;
        float x0f = floorf(xf), y0f = floorf(yf);
        int ix = (int)x0f, iy = (int)y0f;
        float wx1 = xf - x0f, wy1 = yf - y0f;
        float wx0 = 1.f - wx1, wy0 = 1.f - wy1;
        const float* vb = vbase + (size_t)s * 256;
        bool xin0 = (ix >= 0) && (ix < HW);
        bool xin1 = (ix + 1 >= 0) && (ix + 1 < HW);
        bool yin0 = (iy >= 0) && (iy < HW);
        bool yin1 = (iy + 1 >= 0) && (iy + 1 < HW);
        float smp = 0.f;
        if (xin0 && yin0) smp += wx0 * wy0 * vb[(size_t)(iy * HW + ix) * 256];
        if (xin1 && yin0) smp += wx1 * wy0 * vb[(size_t)(iy * HW + ix + 1) * 256];
        if (xin0 && yin1) smp += wx0 * wy1 * vb[(size_t)((iy + 1) * HW + ix) * 256];
        if (xin1 && yin1) smp += wx1 * wy1 * vb[(size_t)((iy + 1) * HW + ix + 1) * 256];
        acc += a * smp;
    }
    attn[(size_t)row * 256 + h * 32 + lane] = acc;
}

// ---------------- residual add + LayerNorm ----------------
__global__ void __launch_bounds__(256) add_ln_kernel(
    const float* __restrict__ x, const float* __restrict__ dlt,
    const float* __restrict__ g, const float* __restrict__ be,
    float* __restrict__ out)
{
    __shared__ float sh[8];
    __shared__ float bcast;
    int row = blockIdx.x, tid = threadIdx.x;
    float v = x[(size_t)row * DM + tid] + dlt[(size_t)row * DM + tid];

    float s = v;
#pragma unroll
    for (int o = 16; o; o >>= 1) s += __shfl_down_sync(0xffffffffu, s, o);
    if ((tid & 31) == 0) sh[tid >> 5] = s;
    __syncthreads();
    if (tid < 8) {
        float t2 = sh[tid];
#pragma unroll
        for (int o = 4; o; o >>= 1) t2 += __shfl_down_sync(0xffu, t2, o);
        if (tid == 0) bcast = t2;
    }
    __syncthreads();
    float mean = bcast * (1.0f / DM);
    float d = v - mean;

    __syncthreads();  // protect sh/bcast reuse
    float s2 = d * d;
#pragma unroll
    for (int o = 16; o; o >>= 1) s2 += __shfl_down_sync(0xffffffffu, s2, o);
    if ((tid & 31) == 0) sh[tid >> 5] = s2;
    __syncthreads();
    if (tid < 8) {
        float t2 = sh[tid];
#pragma unroll
        for (int o = 4; o; o >>= 1) t2 += __shfl_down_sync(0xffu, t2, o);
        if (tid == 0) bcast = t2;
    }
    __syncthreads();
    float var = bcast * (1.0f / DM);
    out[(size_t)row * DM + tid] = d * rsqrtf(var + 1e-5f) * g[tid] + be[tid];
}

// ---------------- launch ----------------
extern "C" void kernel_launch(void* const* d_in, const int* in_sizes, int n_in,
                              void* d_out, int out_size)
{
    (void)in_sizes; (void)n_in; (void)out_size;
    const float* src  = (const float*)d_in[0];
    const float* pos  = (const float*)d_in[1];
    const float* vr   = (const float*)d_in[2];
    const float* Wv   = (const float*)d_in[3];
    const float* bv   = (const float*)d_in[4];
    const float* Woff = (const float*)d_in[5];
    const float* boff = (const float*)d_in[6];
    const float* Wa   = (const float*)d_in[7];
    const float* ba   = (const float*)d_in[8];
    const float* Wo   = (const float*)d_in[9];
    const float* bo   = (const float*)d_in[10];
    const float* g1   = (const float*)d_in[11];
    const float* be1  = (const float*)d_in[12];
    const float* Wl1  = (const float*)d_in[13];
    const float* bl1  = (const float*)d_in[14];
    const float* Wl2  = (const float*)d_in[15];
    const float* bl2  = (const float*)d_in[16];
    const float* g2   = (const float*)d_in[17];
    const float* be2  = (const float*)d_in[18];
    float* out = (float*)d_out;

    float *x, *val, *off, *aw, *attn, *tmp, *ffn, *ref;
    cudaGetSymbolAddress((void**)&x,    g_x);
    cudaGetSymbolAddress((void**)&val,  g_val);
    cudaGetSymbolAddress((void**)&off,  g_off);
    cudaGetSymbolAddress((void**)&aw,   g_aw);
    cudaGetSymbolAddress((void**)&attn, g_attn);
    cudaGetSymbolAddress((void**)&tmp,  g_tmp);
    cudaGetSymbolAddress((void**)&ffn,  g_ffn);
    cudaGetSymbolAddress((void**)&ref,  g_ref);

    int n4 = MROWS * DM / 4;
    copy_kernel<<<(n4 + 255) / 256, 256>>>((float4*)x, (const float4*)src, n4);
    refpts_kernel<<<(MROWS + 255) / 256, 256>>>(vr, ref);

    dim3 gDM(DM / BN, MROWS / BM);     // (4, 170)
    dim3 gAW(128 / BN, MROWS / BM);    // (2, 170)
    dim3 gFF(DFFN / BN, MROWS / BM);   // (16, 170)

    for (int l = 0; l < NLAYERS; l++) {
        gemm_kernel<false, false><<<gDM, 256>>>(x, nullptr,
            Wv + (size_t)l * DM * DM, bv + l * DM, val, DM, DM);
        gemm_kernel<false, true ><<<gDM, 256>>>(x, pos,
            Woff + (size_t)l * DM * 256, boff + l * 256, off, DM, 256);
        gemm_kernel<false, true ><<<gAW, 256>>>(x, pos,
            Wa + (size_t)l * DM * 128, ba + l * 128, aw, DM, 128);
        softmax_kernel<<<(MROWS * NH + 255) / 256, 256>>>(aw);
        sample_kernel<<<MROWS, 256>>>(val, off, aw, ref, attn);
        gemm_kernel<false, false><<<gDM, 256>>>(attn, nullptr,
            Wo + (size_t)l * DM * DM, bo + l * DM, tmp, DM, DM);
        add_ln_kernel<<<MROWS, 256>>>(x, tmp, g1 + l * DM, be1 + l * DM, x);
        gemm_kernel<true , false><<<gFF, 256>>>(x, nullptr,
            Wl1 + (size_t)l * DM * DFFN, bl1 + l * DFFN, ffn, DM, DFFN);
        gemm_kernel<false, false><<<gDM, 256>>>(ffn, nullptr,
            Wl2 + (size_t)l * DFFN * DM, bl2 + l * DM, tmp, DFFN, DM);
        add_ln_kernel<<<MROWS, 256>>>(x, tmp, g2 + l * DM, be2 + l * DM,
                                      (l == NLAYERS - 1) ? out : x);
    }
}

// round 2
// speedup vs baseline: 1.9366x; 1.9366x over previous
#include <cuda_runtime.h>
#include <math.h>

#define LEN 5440
#define NBATCH 2
#define MROWS (NBATCH*LEN)   /* 10880 */
#define DM 256
#define NH 8
#define DFFN 1024
#define NLAYERS 2

// tensor-core GEMM tile
#define BM 128
#define BN 64
#define BK 32

__constant__ int c_HW[4] = {64, 32, 16, 8};
__constant__ int c_S[4]  = {0, 4096, 5120, 5376};

// ---------------- scratch (device globals; no allocation) ----------------
__device__ __align__(16) float g_x[MROWS * DM];
__device__ __align__(16) float g_val[MROWS * DM];
__device__ __align__(16) float g_off[MROWS * DM];
__device__ __align__(16) float g_aw[MROWS * NH * 16];
__device__ __align__(16) float g_attn[MROWS * DM];
__device__ __align__(16) float g_tmp[MROWS * DM];
__device__ __align__(16) float g_ffn[MROWS * DFFN];
__device__ __align__(16) float g_ref[MROWS * 8];

// ---------------- helpers ----------------
__device__ __forceinline__ unsigned tf32_of(float v) {
    unsigned r;
    asm("cvt.rna.tf32.f32 %0, %1;" : "=r"(r) : "f"(v));
    return r;
}

// ---------------- copy ----------------
__global__ void copy_kernel(float4* __restrict__ dst, const float4* __restrict__ src, int n4) {
    int i = blockIdx.x * blockDim.x + threadIdx.x;
    if (i < n4) dst[i] = src[i];
}

// ---------------- reference points ----------------
__global__ void refpts_kernel(const float* __restrict__ vr, float* __restrict__ ref) {
    int idx = blockIdx.x * blockDim.x + threadIdx.x;   // n*LEN + t
    if (idx >= MROWS) return;
    int n = idx / LEN, t = idx % LEN;
    int lvl = 3;
    if (t < 4096) lvl = 0; else if (t < 5120) lvl = 1; else if (t < 5376) lvl = 2;
    int s = c_S[lvl], hw = c_HW[lvl];
    int local = t - s;
    int i = local / hw, j = local % hw;
    float ry = (i + 0.5f) / (vr[(n * 4 + lvl) * 2 + 1] * (float)hw);
    float rx = (j + 0.5f) / (vr[(n * 4 + lvl) * 2 + 0] * (float)hw);
#pragma unroll
    for (int l2 = 0; l2 < 4; l2++) {
        ref[idx * 8 + l2 * 2 + 0] = rx * vr[(n * 4 + l2) * 2 + 0];
        ref[idx * 8 + l2 * 2 + 1] = ry * vr[(n * 4 + l2) * 2 + 1];
    }
}

// ---------------- tensor-core GEMM (tf32 mma.sync) ----------------
// C[M,Nc] = (A (+A2)) @ W + bias, optional ReLU.
// M % 128 == 0, Nc % 64 == 0, K % 32 == 0 (true here: M=10880, Nc in {128,256,1024}, K in {256,1024}).
template <bool RELU, bool POSADD>
__global__ void __launch_bounds__(256, 2) gemm_tc(
    const float* __restrict__ A, const float* __restrict__ A2,
    const float* __restrict__ W, const float* __restrict__ bias,
    float* __restrict__ C, int K, int Nc)
{
    __shared__ unsigned As[BM][BK + 4];   // tf32 bits, stride 36 -> conflict-free frag loads
    __shared__ unsigned Bs[BK][BN + 8];   // tf32 bits, stride 72 -> conflict-free frag loads

    int tid  = threadIdx.x;
    int lane = tid & 31;
    int warp = tid >> 5;
    int wm = warp >> 1;       // 0..3  (M dir, 32 rows each)
    int wn = warp & 1;        // 0..1  (N dir, 32 cols each)
    int gid = lane >> 2;      // 0..7
    int tq  = lane & 3;       // 0..3

    int rowBase = blockIdx.y * BM;
    int colBase = blockIdx.x * BN;

    // global load mapping
    int ar = tid >> 3;            // 0..31 (+32 strided, 4 iters)
    int ac = (tid & 7) * 4;       // 0..28
    int br = tid >> 4;            // 0..15 (+16, 2 iters)
    int bc = (tid & 15) * 4;      // 0..60

    const float* Aptr  = A  + (size_t)(rowBase + ar) * K + ac;
    const float* A2ptr = POSADD ? (A2 + (size_t)(rowBase + ar) * K + ac) : nullptr;
    const float* Wptr  = W + (size_t)br * Nc + colBase + bc;

    float c[2][4][4];
#pragma unroll
    for (int i = 0; i < 2; i++)
#pragma unroll
        for (int j = 0; j < 4; j++)
#pragma unroll
            for (int r = 0; r < 4; r++) c[i][j][r] = 0.f;

    float4 aReg[4], bReg[2];

    // prologue: fetch tile 0
#pragma unroll
    for (int i = 0; i < 4; i++) {
        aReg[i] = *(const float4*)(Aptr + (size_t)(32 * i) * K);
        if (POSADD) {
            float4 pv = *(const float4*)(A2ptr + (size_t)(32 * i) * K);
            aReg[i].x += pv.x; aReg[i].y += pv.y; aReg[i].z += pv.z; aReg[i].w += pv.w;
        }
    }
#pragma unroll
    for (int i = 0; i < 2; i++)
        bReg[i] = *(const float4*)(Wptr + (size_t)(16 * i) * Nc);

    for (int k0 = 0; k0 < K; k0 += BK) {
        // store current tile to smem (with tf32 conversion)
#pragma unroll
        for (int i = 0; i < 4; i++) {
            As[ar + 32 * i][ac + 0] = tf32_of(aReg[i].x);
            As[ar + 32 * i][ac + 1] = tf32_of(aReg[i].y);
            As[ar + 32 * i][ac + 2] = tf32_of(aReg[i].z);
            As[ar + 32 * i][ac + 3] = tf32_of(aReg[i].w);
        }
#pragma unroll
        for (int i = 0; i < 2; i++) {
            Bs[br + 16 * i][bc + 0] = tf32_of(bReg[i].x);
            Bs[br + 16 * i][bc + 1] = tf32_of(bReg[i].y);
            Bs[br + 16 * i][bc + 2] = tf32_of(bReg[i].z);
            Bs[br + 16 * i][bc + 3] = tf32_of(bReg[i].w);
        }
        __syncthreads();

        // prefetch next tile
        if (k0 + BK < K) {
#pragma unroll
            for (int i = 0; i < 4; i++) {
                aReg[i] = *(const float4*)(Aptr + (size_t)(32 * i) * K + k0 + BK);
                if (POSADD) {
                    float4 pv = *(const float4*)(A2ptr + (size_t)(32 * i) * K + k0 + BK);
                    aReg[i].x += pv.x; aReg[i].y += pv.y; aReg[i].z += pv.z; aReg[i].w += pv.w;
                }
            }
#pragma unroll
            for (int i = 0; i < 2; i++)
                bReg[i] = *(const float4*)(Wptr + (size_t)(k0 + BK + 16 * i) * Nc);
        }

        // compute
#pragma unroll
        for (int ks = 0; ks < 4; ks++) {
            int k = ks * 8;
            unsigned a[2][4];
#pragma unroll
            for (int mt = 0; mt < 2; mt++) {
                int r = wm * 32 + mt * 16;
                a[mt][0] = As[r + gid][k + tq];
                a[mt][1] = As[r + gid + 8][k + tq];
                a[mt][2] = As[r + gid][k + tq + 4];
                a[mt][3] = As[r + gid + 8][k + tq + 4];
            }
#pragma unroll
            for (int nt = 0; nt < 4; nt++) {
                int cn = wn * 32 + nt * 8 + gid;
                unsigned b0 = Bs[k + tq][cn];
                unsigned b1 = Bs[k + tq + 4][cn];
#pragma unroll
                for (int mt = 0; mt < 2; mt++) {
                    asm volatile(
                        "mma.sync.aligned.m16n8k8.row.col.f32.tf32.tf32.f32 "
                        "{%0,%1,%2,%3}, {%4,%5,%6,%7}, {%8,%9}, {%0,%1,%2,%3};\n"
                        : "+f"(c[mt][nt][0]), "+f"(c[mt][nt][1]),
                          "+f"(c[mt][nt][2]), "+f"(c[mt][nt][3])
                        : "r"(a[mt][0]), "r"(a[mt][1]), "r"(a[mt][2]), "r"(a[mt][3]),
                          "r"(b0), "r"(b1));
                }
            }
        }
        __syncthreads();
    }

    // epilogue
#pragma unroll
    for (int mt = 0; mt < 2; mt++) {
#pragma unroll
        for (int nt = 0; nt < 4; nt++) {
            int r0 = rowBase + wm * 32 + mt * 16 + gid;
            int cc = colBase + wn * 32 + nt * 8 + tq * 2;
            float b0v = bias[cc], b1v = bias[cc + 1];
            float v0 = c[mt][nt][0] + b0v, v1 = c[mt][nt][1] + b1v;
            float v2 = c[mt][nt][2] + b0v, v3 = c[mt][nt][3] + b1v;
            if (RELU) {
                v0 = fmaxf(v0, 0.f); v1 = fmaxf(v1, 0.f);
                v2 = fmaxf(v2, 0.f); v3 = fmaxf(v3, 0.f);
            }
            *(float2*)(C + (size_t)r0 * Nc + cc)       = make_float2(v0, v1);
            *(float2*)(C + (size_t)(r0 + 8) * Nc + cc) = make_float2(v2, v3);
        }
    }
}

// ---------------- softmax over groups of 16 ----------------
__global__ void softmax_kernel(float* __restrict__ aw) {
    int g = blockIdx.x * blockDim.x + threadIdx.x;
    if (g >= MROWS * NH) return;
    float* p = aw + (size_t)g * 16;
    float e[16];
    float mx = -1e30f;
#pragma unroll
    for (int i = 0; i < 16; i++) { e[i] = p[i]; mx = fmaxf(mx, e[i]); }
    float s = 0.f;
#pragma unroll
    for (int i = 0; i < 16; i++) { e[i] = expf(e[i] - mx); s += e[i]; }
    float inv = 1.f / s;
#pragma unroll
    for (int i = 0; i < 16; i++) p[i] = e[i] * inv;
}

// ---------------- deformable bilinear sampling ----------------
__global__ void __launch_bounds__(256) sample_kernel(
    const float* __restrict__ value, const float* __restrict__ off,
    const float* __restrict__ aw, const float* __restrict__ ref,
    float* __restrict__ attn)
{
    int row = blockIdx.x;              // n*LEN + t
    int h = threadIdx.x >> 5;          // head
    int lane = threadIdx.x & 31;       // head-dim channel
    int n = row / LEN;

    float offv = off[(size_t)row * 256 + h * 32 + lane];
    float awv  = (lane < 16) ? aw[(size_t)row * 128 + h * 16 + lane] : 0.f;
    float refv = (lane < 8)  ? ref[(size_t)row * 8 + lane] : 0.f;

    const float* vbase = value + (size_t)n * LEN * 256 + h * 32 + lane;
    float acc = 0.f;
#pragma unroll
    for (int p = 0; p < 16; p++) {
        int lvl = p >> 2;
        float ox = __shfl_sync(0xffffffffu, offv, 2 * p);
        float oy = __shfl_sync(0xffffffffu, offv, 2 * p + 1);
        float a  = __shfl_sync(0xffffffffu, awv, p);
        float rx = __shfl_sync(0xffffffffu, refv, 2 * lvl);
        float ry = __shfl_sync(0xffffffffu, refv, 2 * lvl + 1);
        int HW = c_HW[lvl], s = c_S[lvl];
        float fw = (float)HW;
        float xf = (rx + ox / fw) * fw - 0.5f;
        float yf = (ry + oy / fw) * fw - 0.5f;
        float x0f = floorf(xf), y0f = floorf(yf);
        int ix = (int)x0f, iy = (int)y0f;
        float wx1 = xf - x0f, wy1 = yf - y0f;
        float wx0 = 1.f - wx1, wy0 = 1.f - wy1;
        const float* vb = vbase + (size_t)s * 256;
        bool xin0 = (ix >= 0) && (ix < HW);
        bool xin1 = (ix + 1 >= 0) && (ix + 1 < HW);
        bool yin0 = (iy >= 0) && (iy < HW);
        bool yin1 = (iy + 1 >= 0) && (iy + 1 < HW);
        float smp = 0.f;
        if (xin0 && yin0) smp += wx0 * wy0 * vb[(size_t)(iy * HW + ix) * 256];
        if (xin1 && yin0) smp += wx1 * wy0 * vb[(size_t)(iy * HW + ix + 1) * 256];
        if (xin0 && yin1) smp += wx0 * wy1 * vb[(size_t)((iy + 1) * HW + ix) * 256];
        if (xin1 && yin1) smp += wx1 * wy1 * vb[(size_t)((iy + 1) * HW + ix + 1) * 256];
        acc += a * smp;
    }
    attn[(size_t)row * 256 + h * 32 + lane] = acc;
}

// ---------------- residual add + LayerNorm ----------------
__global__ void __launch_bounds__(256) add_ln_kernel(
    const float* __restrict__ x, const float* __restrict__ dlt,
    const float* __restrict__ g, const float* __restrict__ be,
    float* __restrict__ out)
{
    __shared__ float sh[8];
    __shared__ float bcast;
    int row = blockIdx.x, tid = threadIdx.x;
    float v = x[(size_t)row * DM + tid] + dlt[(size_t)row * DM + tid];

    float s = v;
#pragma unroll
    for (int o = 16; o; o >>= 1) s += __shfl_down_sync(0xffffffffu, s, o);
    if ((tid & 31) == 0) sh[tid >> 5] = s;
    __syncthreads();
    if (tid < 8) {
        float t2 = sh[tid];
#pragma unroll
        for (int o = 4; o; o >>= 1) t2 += __shfl_down_sync(0xffu, t2, o);
        if (tid == 0) bcast = t2;
    }
    __syncthreads();
    float mean = bcast * (1.0f / DM);
    float d = v - mean;

    __syncthreads();
    float s2 = d * d;
#pragma unroll
    for (int o = 16; o; o >>= 1) s2 += __shfl_down_sync(0xffffffffu, s2, o);
    if ((tid & 31) == 0) sh[tid >> 5] = s2;
    __syncthreads();
    if (tid < 8) {
        float t2 = sh[tid];
#pragma unroll
        for (int o = 4; o; o >>= 1) t2 += __shfl_down_sync(0xffu, t2, o);
        if (tid == 0) bcast = t2;
    }
    __syncthreads();
    float var = bcast * (1.0f / DM);
    out[(size_t)row * DM + tid] = d * rsqrtf(var + 1e-5f) * g[tid] + be[tid];
}

// ---------------- launch ----------------
extern "C" void kernel_launch(void* const* d_in, const int* in_sizes, int n_in,
                              void* d_out, int out_size)
{
    (void)in_sizes; (void)n_in; (void)out_size;
    const float* src  = (const float*)d_in[0];
    const float* pos  = (const float*)d_in[1];
    const float* vr   = (const float*)d_in[2];
    const float* Wv   = (const float*)d_in[3];
    const float* bv   = (const float*)d_in[4];
    const float* Woff = (const float*)d_in[5];
    const float* boff = (const float*)d_in[6];
    const float* Wa   = (const float*)d_in[7];
    const float* ba   = (const float*)d_in[8];
    const float* Wo   = (const float*)d_in[9];
    const float* bo   = (const float*)d_in[10];
    const float* g1   = (const float*)d_in[11];
    const float* be1  = (const float*)d_in[12];
    const float* Wl1  = (const float*)d_in[13];
    const float* bl1  = (const float*)d_in[14];
    const float* Wl2  = (const float*)d_in[15];
    const float* bl2  = (const float*)d_in[16];
    const float* g2   = (const float*)d_in[17];
    const float* be2  = (const float*)d_in[18];
    float* out = (float*)d_out;

    float *x, *val, *off, *aw, *attn, *tmp, *ffn, *ref;
    cudaGetSymbolAddress((void**)&x,    g_x);
    cudaGetSymbolAddress((void**)&val,  g_val);
    cudaGetSymbolAddress((void**)&off,  g_off);
    cudaGetSymbolAddress((void**)&aw,   g_aw);
    cudaGetSymbolAddress((void**)&attn, g_attn);
    cudaGetSymbolAddress((void**)&tmp,  g_tmp);
    cudaGetSymbolAddress((void**)&ffn,  g_ffn);
    cudaGetSymbolAddress((void**)&ref,  g_ref);

    int n4 = MROWS * DM / 4;
    copy_kernel<<<(n4 + 255) / 256, 256>>>((float4*)x, (const float4*)src, n4);
    refpts_kernel<<<(MROWS + 255) / 256, 256>>>(vr, ref);

    dim3 gDM(DM / BN, MROWS / BM);     // (4, 85)
    dim3 gAW(128 / BN, MROWS / BM);    // (2, 85)
    dim3 gFF(DFFN / BN, MROWS / BM);   // (16, 85)

    for (int l = 0; l < NLAYERS; l++) {
        gemm_tc<false, false><<<gDM, 256>>>(x, nullptr,
            Wv + (size_t)l * DM * DM, bv + l * DM, val, DM, DM);
        gemm_tc<false, true ><<<gDM, 256>>>(x, pos,
            Woff + (size_t)l * DM * 256, boff + l * 256, off, DM, 256);
        gemm_tc<false, true ><<<gAW, 256>>>(x, pos,
            Wa + (size_t)l * DM * 128, ba + l * 128, aw, DM, 128);
        softmax_kernel<<<(MROWS * NH + 255) / 256, 256>>>(aw);
        sample_kernel<<<MROWS, 256>>>(val, off, aw, ref, attn);
        gemm_tc<false, false><<<gDM, 256>>>(attn, nullptr,
            Wo + (size_t)l * DM * DM, bo + l * DM, tmp, DM, DM);
        add_ln_kernel<<<MROWS, 256>>>(x, tmp, g1 + l * DM, be1 + l * DM, x);
        gemm_tc<true , false><<<gFF, 256>>>(x, nullptr,
            Wl1 + (size_t)l * DM * DFFN, bl1 + l * DFFN, ffn, DM, DFFN);
        gemm_tc<false, false><<<gDM, 256>>>(ffn, nullptr,
            Wl2 + (size_t)l * DFFN * DM, bl2 + l * DM, tmp, DFFN, DM);
        add_ln_kernel<<<MROWS, 256>>>(x, tmp, g2 + l * DM, be2 + l * DM,
                                      (l == NLAYERS - 1) ? out : x);
    }
}

// round 3
// speedup vs baseline: 1.9624x; 1.0133x over previous
#include <cuda_runtime.h>
#include <math.h>

#define LEN 5440
#define NBATCH 2
#define MROWS (NBATCH*LEN)   /* 10880 */
#define DM 256
#define NH 8
#define DFFN 1024
#define NLAYERS 2

// tensor-core GEMM tile
#define BM 128
#define BN 64
#define BK 32
#define NSTAGE 3
#define A_LD 36            /* As row stride (elems) */
#define B_LD 72            /* Bs row stride (elems) */
#define ASTRIDE (BM*A_LD)  /* per-stage A elems = 4608 */
#define BSTRIDE (BK*B_LD)  /* per-stage B elems = 2304 */
#define SMEM_ELEMS (NSTAGE*(ASTRIDE+BSTRIDE))
#define SMEM_BYTES (SMEM_ELEMS*4)   /* 82944 */

__constant__ int c_HW[4] = {64, 32, 16, 8};
__constant__ int c_S[4]  = {0, 4096, 5120, 5376};

// ---------------- scratch (device globals; no allocation) ----------------
__device__ __align__(16) float    g_x[MROWS * DM];
__device__ __align__(16) unsigned g_xt[MROWS * DM];     // tf32(x)
__device__ __align__(16) unsigned g_qt[MROWS * DM];     // tf32(x+pos)
__device__ __align__(16) float    g_val[MROWS * DM];
__device__ __align__(16) float    g_off[MROWS * DM];
__device__ __align__(16) float    g_aw[MROWS * NH * 16];
__device__ __align__(16) unsigned g_attnt[MROWS * DM];  // tf32(attn)
__device__ __align__(16) float    g_tmp[MROWS * DM];
__device__ __align__(16) unsigned g_ffnt[MROWS * DFFN]; // tf32(relu(ffn))
__device__ __align__(16) float    g_ref[MROWS * 8];
// converted weights
__device__ __align__(16) unsigned g_wvt[NLAYERS * DM * DM];
__device__ __align__(16) unsigned g_wofft[NLAYERS * DM * DM];
__device__ __align__(16) unsigned g_wat[NLAYERS * DM * 128];
__device__ __align__(16) unsigned g_wot[NLAYERS * DM * DM];
__device__ __align__(16) unsigned g_wl1t[NLAYERS * DM * DFFN];
__device__ __align__(16) unsigned g_wl2t[NLAYERS * DFFN * DM];

// ---------------- helpers ----------------
__device__ __forceinline__ unsigned tf32_of(float v) {
    unsigned r;
    asm("cvt.rna.tf32.f32 %0, %1;" : "=r"(r) : "f"(v));
    return r;
}
__device__ __forceinline__ void cpa16(unsigned saddr, const void* g) {
    asm volatile("cp.async.cg.shared.global [%0], [%1], 16;" :: "r"(saddr), "l"(g));
}

// ---------------- weight conversion ----------------
__global__ void cvtw_kernel(const float* __restrict__ w, unsigned* __restrict__ o, int n) {
    int i = blockIdx.x * blockDim.x + threadIdx.x;
    if (i < n) o[i] = tf32_of(w[i]);
}

// ---------------- init: x, tf32(x), tf32(x+pos) ----------------
__global__ void init_kernel(const float* __restrict__ src, const float* __restrict__ pos,
                            float* __restrict__ x, unsigned* __restrict__ xt,
                            unsigned* __restrict__ qt, int n) {
    int i = blockIdx.x * blockDim.x + threadIdx.x;
    if (i >= n) return;
    float s = src[i];
    x[i] = s;
    xt[i] = tf32_of(s);
    qt[i] = tf32_of(s + pos[i]);
}

// ---------------- reference points ----------------
__global__ void refpts_kernel(const float* __restrict__ vr, float* __restrict__ ref) {
    int idx = blockIdx.x * blockDim.x + threadIdx.x;
    if (idx >= MROWS) return;
    int n = idx / LEN, t = idx % LEN;
    int lvl = 3;
    if (t < 4096) lvl = 0; else if (t < 5120) lvl = 1; else if (t < 5376) lvl = 2;
    int s = c_S[lvl], hw = c_HW[lvl];
    int local = t - s;
    int i = local / hw, j = local % hw;
    float ry = (i + 0.5f) / (vr[(n * 4 + lvl) * 2 + 1] * (float)hw);
    float rx = (j + 0.5f) / (vr[(n * 4 + lvl) * 2 + 0] * (float)hw);
#pragma unroll
    for (int l2 = 0; l2 < 4; l2++) {
        ref[idx * 8 + l2 * 2 + 0] = rx * vr[(n * 4 + l2) * 2 + 0];
        ref[idx * 8 + l2 * 2 + 1] = ry * vr[(n * 4 + l2) * 2 + 1];
    }
}

// ---------------- tensor-core GEMM (tf32 mma.sync + cp.async 3-stage) ----------------
// A, W pre-converted to tf32 bits. C[M,Nc] = A@W + bias.
// RELU_CVT: relu then store tf32 bits (for FFN mid). Else store fp32.
// M%128==0, Nc%64==0, K%32==0.
template <bool RELU_CVT>
__global__ void __launch_bounds__(256) gemm_tc(
    const unsigned* __restrict__ A, const unsigned* __restrict__ W,
    const float* __restrict__ bias, float* __restrict__ C, int K, int Nc)
{
    extern __shared__ unsigned sm[];
    unsigned sbase = (unsigned)__cvta_generic_to_shared(sm);

    int tid  = threadIdx.x;
    int lane = tid & 31;
    int warp = tid >> 5;
    int wm = warp >> 1;       // 0..3
    int wn = warp & 1;        // 0..1
    int gid = lane >> 2;      // 0..7
    int tq  = lane & 3;       // 0..3

    int rowBase = blockIdx.y * BM;
    int colBase = blockIdx.x * BN;

    int ar = tid >> 3;            // 0..31 (+32*i)
    int ac = (tid & 7) * 4;
    int br = tid >> 4;            // 0..15 (+16*i)
    int bc = (tid & 15) * 4;

    const unsigned* Ag = A + (size_t)(rowBase + ar) * K + ac;
    const unsigned* Wg = W + (size_t)br * Nc + colBase + bc;

    unsigned adst0 = sbase + (unsigned)(ar * A_LD + ac) * 4u;
    unsigned bdst0 = sbase + (unsigned)(NSTAGE * ASTRIDE + br * B_LD + bc) * 4u;

    auto issue = [&](int s, int k0) {
        unsigned ad = adst0 + (unsigned)(s * ASTRIDE) * 4u;
#pragma unroll
        for (int i = 0; i < 4; i++)
            cpa16(ad + (unsigned)(32 * i * A_LD) * 4u, Ag + (size_t)(32 * i) * K + k0);
        unsigned bd = bdst0 + (unsigned)(s * BSTRIDE) * 4u;
#pragma unroll
        for (int i = 0; i < 2; i++)
            cpa16(bd + (unsigned)(16 * i * B_LD) * 4u, Wg + (size_t)(k0 + 16 * i) * Nc);
        asm volatile("cp.async.commit_group;");
    };

    float c[2][4][4];
#pragma unroll
    for (int i = 0; i < 2; i++)
#pragma unroll
        for (int j = 0; j < 4; j++)
#pragma unroll
            for (int r = 0; r < 4; r++) c[i][j][r] = 0.f;

    int T = K / BK;
    issue(0, 0);
    issue(1, BK);

    for (int t = 0; t < T; t++) {
        asm volatile("cp.async.wait_group 1;");
        __syncthreads();
        if (t + 2 < T) issue((t + 2) % NSTAGE, (t + 2) * BK);
        else asm volatile("cp.async.commit_group;");

        const unsigned* Asb = sm + (t % NSTAGE) * ASTRIDE;
        const unsigned* Bsb = sm + NSTAGE * ASTRIDE + (t % NSTAGE) * BSTRIDE;

#pragma unroll
        for (int ks = 0; ks < 4; ks++) {
            int k = ks * 8;
            unsigned a[2][4];
#pragma unroll
            for (int mt = 0; mt < 2; mt++) {
                int r = wm * 32 + mt * 16;
                a[mt][0] = Asb[(r + gid) * A_LD + k + tq];
                a[mt][1] = Asb[(r + gid + 8) * A_LD + k + tq];
                a[mt][2] = Asb[(r + gid) * A_LD + k + tq + 4];
                a[mt][3] = Asb[(r + gid + 8) * A_LD + k + tq + 4];
            }
#pragma unroll
            for (int nt = 0; nt < 4; nt++) {
                int cn = wn * 32 + nt * 8 + gid;
                unsigned b0 = Bsb[(k + tq) * B_LD + cn];
                unsigned b1 = Bsb[(k + tq + 4) * B_LD + cn];
#pragma unroll
                for (int mt = 0; mt < 2; mt++) {
                    asm volatile(
                        "mma.sync.aligned.m16n8k8.row.col.f32.tf32.tf32.f32 "
                        "{%0,%1,%2,%3}, {%4,%5,%6,%7}, {%8,%9}, {%0,%1,%2,%3};\n"
                        : "+f"(c[mt][nt][0]), "+f"(c[mt][nt][1]),
                          "+f"(c[mt][nt][2]), "+f"(c[mt][nt][3])
                        : "r"(a[mt][0]), "r"(a[mt][1]), "r"(a[mt][2]), "r"(a[mt][3]),
                          "r"(b0), "r"(b1));
                }
            }
        }
        __syncthreads();
    }

    // epilogue
#pragma unroll
    for (int mt = 0; mt < 2; mt++) {
#pragma unroll
        for (int nt = 0; nt < 4; nt++) {
            int r0 = rowBase + wm * 32 + mt * 16 + gid;
            int cc = colBase + wn * 32 + nt * 8 + tq * 2;
            float b0v = bias[cc], b1v = bias[cc + 1];
            float v0 = c[mt][nt][0] + b0v, v1 = c[mt][nt][1] + b1v;
            float v2 = c[mt][nt][2] + b0v, v3 = c[mt][nt][3] + b1v;
            if (RELU_CVT) {
                uint2 p0, p1;
                p0.x = tf32_of(fmaxf(v0, 0.f)); p0.y = tf32_of(fmaxf(v1, 0.f));
                p1.x = tf32_of(fmaxf(v2, 0.f)); p1.y = tf32_of(fmaxf(v3, 0.f));
                *(uint2*)((unsigned*)C + (size_t)r0 * Nc + cc)       = p0;
                *(uint2*)((unsigned*)C + (size_t)(r0 + 8) * Nc + cc) = p1;
            } else {
                *(float2*)(C + (size_t)r0 * Nc + cc)       = make_float2(v0, v1);
                *(float2*)(C + (size_t)(r0 + 8) * Nc + cc) = make_float2(v2, v3);
            }
        }
    }
}

// ---------------- softmax over groups of 16 ----------------
__global__ void softmax_kernel(float* __restrict__ aw) {
    int g = blockIdx.x * blockDim.x + threadIdx.x;
    if (g >= MROWS * NH) return;
    float* p = aw + (size_t)g * 16;
    float e[16];
    float mx = -1e30f;
#pragma unroll
    for (int i = 0; i < 16; i++) { e[i] = p[i]; mx = fmaxf(mx, e[i]); }
    float s = 0.f;
#pragma unroll
    for (int i = 0; i < 16; i++) { e[i] = expf(e[i] - mx); s += e[i]; }
    float inv = 1.f / s;
#pragma unroll
    for (int i = 0; i < 16; i++) p[i] = e[i] * inv;
}

// ---------------- deformable bilinear sampling (writes tf32 attn) ----------------
__global__ void __launch_bounds__(256) sample_kernel(
    const float* __restrict__ value, const float* __restrict__ off,
    const float* __restrict__ aw, const float* __restrict__ ref,
    unsigned* __restrict__ attnt)
{
    int row = blockIdx.x;
    int h = threadIdx.x >> 5;
    int lane = threadIdx.x & 31;
    int n = row / LEN;

    float offv = off[(size_t)row * 256 + h * 32 + lane];
    float awv  = (lane < 16) ? aw[(size_t)row * 128 + h * 16 + lane] : 0.f;
    float refv = (lane < 8)  ? ref[(size_t)row * 8 + lane] : 0.f;

    const float* vbase = value + (size_t)n * LEN * 256 + h * 32 + lane;
    float acc = 0.f;
#pragma unroll
    for (int p = 0; p < 16; p++) {
        int lvl = p >> 2;
        float ox = __shfl_sync(0xffffffffu, offv, 2 * p);
        float oy = __shfl_sync(0xffffffffu, offv, 2 * p + 1);
        float a  = __shfl_sync(0xffffffffu, awv, p);
        float rx = __shfl_sync(0xffffffffu, refv, 2 * lvl);
        float ry = __shfl_sync(0xffffffffu, refv, 2 * lvl + 1);
        int HW = c_HW[lvl], s = c_S[lvl];
        float fw = (float)HW;
        float xf = (rx + ox / fw) * fw - 0.5f;
        float yf = (ry + oy / fw) * fw - 0.5f;
        float x0f = floorf(xf), y0f = floorf(yf);
        int ix = (int)x0f, iy = (int)y0f;
        float wx1 = xf - x0f, wy1 = yf - y0f;
        float wx0 = 1.f - wx1, wy0 = 1.f - wy1;
        const float* vb = vbase + (size_t)s * 256;
        bool xin0 = (ix >= 0) && (ix < HW);
        bool xin1 = (ix + 1 >= 0) && (ix + 1 < HW);
        bool yin0 = (iy >= 0) && (iy < HW);
        bool yin1 = (iy + 1 >= 0) && (iy + 1 < HW);
        float smp = 0.f;
        if (xin0 && yin0) smp += wx0 * wy0 * vb[(size_t)(iy * HW + ix) * 256];
        if (xin1 && yin0) smp += wx1 * wy0 * vb[(size_t)(iy * HW + ix + 1) * 256];
        if (xin0 && yin1) smp += wx0 * wy1 * vb[(size_t)((iy + 1) * HW + ix) * 256];
        if (xin1 && yin1) smp += wx1 * wy1 * vb[(size_t)((iy + 1) * HW + ix + 1) * 256];
        acc += a * smp;
    }
    attnt[(size_t)row * 256 + h * 32 + lane] = tf32_of(acc);
}

// ---------------- residual add + LayerNorm (+optional tf32 aux outputs) ----------------
template <bool AUX>
__global__ void __launch_bounds__(256) add_ln_kernel(
    const float* __restrict__ x, const float* __restrict__ dlt,
    const float* __restrict__ g, const float* __restrict__ be,
    const float* __restrict__ pos,
    float* __restrict__ out, unsigned* __restrict__ xt, unsigned* __restrict__ qt)
{
    __shared__ float sh[8];
    __shared__ float bcast;
    int row = blockIdx.x, tid = threadIdx.x;
    float v = x[(size_t)row * DM + tid] + dlt[(size_t)row * DM + tid];

    float s = v;
#pragma unroll
    for (int o = 16; o; o >>= 1) s += __shfl_down_sync(0xffffffffu, s, o);
    if ((tid & 31) == 0) sh[tid >> 5] = s;
    __syncthreads();
    if (tid < 8) {
        float t2 = sh[tid];
#pragma unroll
        for (int o = 4; o; o >>= 1) t2 += __shfl_down_sync(0xffu, t2, o);
        if (tid == 0) bcast = t2;
    }
    __syncthreads();
    float mean = bcast * (1.0f / DM);
    float d = v - mean;

    __syncthreads();
    float s2 = d * d;
#pragma unroll
    for (int o = 16; o; o >>= 1) s2 += __shfl_down_sync(0xffffffffu, s2, o);
    if ((tid & 31) == 0) sh[tid >> 5] = s2;
    __syncthreads();
    if (tid < 8) {
        float t2 = sh[tid];
#pragma unroll
        for (int o = 4; o; o >>= 1) t2 += __shfl_down_sync(0xffu, t2, o);
        if (tid == 0) bcast = t2;
    }
    __syncthreads();
    float var = bcast * (1.0f / DM);
    float r = d * rsqrtf(var + 1e-5f) * g[tid] + be[tid];
    out[(size_t)row * DM + tid] = r;
    if (AUX) {
        xt[(size_t)row * DM + tid] = tf32_of(r);
        qt[(size_t)row * DM + tid] = tf32_of(r + pos[(size_t)row * DM + tid]);
    }
}

// ---------------- launch ----------------
extern "C" void kernel_launch(void* const* d_in, const int* in_sizes, int n_in,
                              void* d_out, int out_size)
{
    (void)in_sizes; (void)n_in; (void)out_size;
    const float* src  = (const float*)d_in[0];
    const float* pos  = (const float*)d_in[1];
    const float* vr   = (const float*)d_in[2];
    const float* Wv   = (const float*)d_in[3];
    const float* bv   = (const float*)d_in[4];
    const float* Woff = (const float*)d_in[5];
    const float* boff = (const float*)d_in[6];
    const float* Wa   = (const float*)d_in[7];
    const float* ba   = (const float*)d_in[8];
    const float* Wo   = (const float*)d_in[9];
    const float* bo   = (const float*)d_in[10];
    const float* g1   = (const float*)d_in[11];
    const float* be1  = (const float*)d_in[12];
    const float* Wl1  = (const float*)d_in[13];
    const float* bl1  = (const float*)d_in[14];
    const float* Wl2  = (const float*)d_in[15];
    const float* bl2  = (const float*)d_in[16];
    const float* g2   = (const float*)d_in[17];
    const float* be2  = (const float*)d_in[18];
    float* out = (float*)d_out;

    float *x, *val, *off, *aw, *tmp, *ref;
    unsigned *xt, *qt, *attnt, *ffnt;
    unsigned *wvt, *wofft, *wat, *wot, *wl1t, *wl2t;
    cudaGetSymbolAddress((void**)&x,     g_x);
    cudaGetSymbolAddress((void**)&xt,    g_xt);
    cudaGetSymbolAddress((void**)&qt,    g_qt);
    cudaGetSymbolAddress((void**)&val,   g_val);
    cudaGetSymbolAddress((void**)&off,   g_off);
    cudaGetSymbolAddress((void**)&aw,    g_aw);
    cudaGetSymbolAddress((void**)&attnt, g_attnt);
    cudaGetSymbolAddress((void**)&tmp,   g_tmp);
    cudaGetSymbolAddress((void**)&ffnt,  g_ffnt);
    cudaGetSymbolAddress((void**)&ref,   g_ref);
    cudaGetSymbolAddress((void**)&wvt,   g_wvt);
    cudaGetSymbolAddress((void**)&wofft, g_wofft);
    cudaGetSymbolAddress((void**)&wat,   g_wat);
    cudaGetSymbolAddress((void**)&wot,   g_wot);
    cudaGetSymbolAddress((void**)&wl1t,  g_wl1t);
    cudaGetSymbolAddress((void**)&wl2t,  g_wl2t);

    cudaFuncSetAttribute(gemm_tc<false>, cudaFuncAttributeMaxDynamicSharedMemorySize, SMEM_BYTES);
    cudaFuncSetAttribute(gemm_tc<true>,  cudaFuncAttributeMaxDynamicSharedMemorySize, SMEM_BYTES);

    // one-time-per-launch conversions
    int n;
    n = NLAYERS * DM * DM;    cvtw_kernel<<<(n + 255) / 256, 256>>>(Wv,   wvt,   n);
    n = NLAYERS * DM * DM;    cvtw_kernel<<<(n + 255) / 256, 256>>>(Woff, wofft, n);
    n = NLAYERS * DM * 128;   cvtw_kernel<<<(n + 255) / 256, 256>>>(Wa,   wat,   n);
    n = NLAYERS * DM * DM;    cvtw_kernel<<<(n + 255) / 256, 256>>>(Wo,   wot,   n);
    n = NLAYERS * DM * DFFN;  cvtw_kernel<<<(n + 255) / 256, 256>>>(Wl1,  wl1t,  n);
    n = NLAYERS * DFFN * DM;  cvtw_kernel<<<(n + 255) / 256, 256>>>(Wl2,  wl2t,  n);

    n = MROWS * DM;
    init_kernel<<<(n + 255) / 256, 256>>>(src, pos, x, xt, qt, n);
    refpts_kernel<<<(MROWS + 255) / 256, 256>>>(vr, ref);

    dim3 gDM(DM / BN, MROWS / BM);     // (4, 85)
    dim3 gAW(128 / BN, MROWS / BM);    // (2, 85)
    dim3 gFF(DFFN / BN, MROWS / BM);   // (16, 85)

    for (int l = 0; l < NLAYERS; l++) {
        gemm_tc<false><<<gDM, 256, SMEM_BYTES>>>(xt, wvt + (size_t)l * DM * DM,
            bv + l * DM, val, DM, DM);
        gemm_tc<false><<<gDM, 256, SMEM_BYTES>>>(qt, wofft + (size_t)l * DM * DM,
            boff + l * 256, off, DM, 256);
        gemm_tc<false><<<gAW, 256, SMEM_BYTES>>>(qt, wat + (size_t)l * DM * 128,
            ba + l * 128, aw, DM, 128);
        softmax_kernel<<<(MROWS * NH + 255) / 256, 256>>>(aw);
        sample_kernel<<<MROWS, 256>>>(val, off, aw, ref, attnt);
        gemm_tc<false><<<gDM, 256, SMEM_BYTES>>>(attnt, wot + (size_t)l * DM * DM,
            bo + l * DM, tmp, DM, DM);
        add_ln_kernel<true><<<MROWS, 256>>>(x, tmp, g1 + l * DM, be1 + l * DM, pos, x, xt, qt);
        gemm_tc<true ><<<gFF, 256, SMEM_BYTES>>>(xt, wl1t + (size_t)l * DM * DFFN,
            bl1 + l * DFFN, (float*)ffnt, DM, DFFN);
        gemm_tc<false><<<gDM, 256, SMEM_BYTES>>>(ffnt, wl2t + (size_t)l * DFFN * DM,
            bl2 + l * DM, tmp, DFFN, DM);
        if (l == NLAYERS - 1)
            add_ln_kernel<false><<<MROWS, 256>>>(x, tmp, g2 + l * DM, be2 + l * DM, pos, out, xt, qt);
        else
            add_ln_kernel<true ><<<MROWS, 256>>>(x, tmp, g2 + l * DM, be2 + l * DM, pos, x, xt, qt);
    }
}

// round 4
// speedup vs baseline: 2.1706x; 1.1061x over previous
#include <cuda_runtime.h>
#include <math.h>

#define LEN 5440
#define NBATCH 2
#define MROWS (NBATCH*LEN)   /* 10880 */
#define DM 256
#define NH 8
#define DFFN 1024
#define NLAYERS 2

// tensor-core GEMM tile
#define BM 128
#define BN 64
#define BK 32
#define NSTAGE 3
#define ASTRIDE (BM*BK)      /* words per A stage = 4096 (16KB) */
#define BSTRIDE (BN*BK)      /* words per B stage = 2048 (8KB)  */
#define SMEM_BYTES (NSTAGE*(ASTRIDE+BSTRIDE)*4)   /* 73728 */

__constant__ int c_HW[4] = {64, 32, 16, 8};
__constant__ int c_S[4]  = {0, 4096, 5120, 5376};

// ---------------- scratch (device globals; no allocation) ----------------
__device__ __align__(16) float    g_x[MROWS * DM];
__device__ __align__(16) unsigned g_xt[MROWS * DM];     // tf32(x)
__device__ __align__(16) unsigned g_qt[MROWS * DM];     // tf32(x+pos)
__device__ __align__(16) float    g_val[MROWS * DM];
__device__ __align__(16) float    g_off[MROWS * DM];
__device__ __align__(16) float    g_aw[MROWS * NH * 16];
__device__ __align__(16) unsigned g_attnt[MROWS * DM];  // tf32(attn)
__device__ __align__(16) float    g_tmp[MROWS * DM];
__device__ __align__(16) unsigned g_ffnt[MROWS * DFFN]; // tf32(relu(ffn))
__device__ __align__(16) float    g_ref[MROWS * 8];
// converted + TRANSPOSED weights: [N][K] k-contiguous, tf32 bits
__device__ __align__(16) unsigned g_wvt[NLAYERS * DM * DM];
__device__ __align__(16) unsigned g_wofft[NLAYERS * DM * DM];
__device__ __align__(16) unsigned g_wat[NLAYERS * DM * 128];
__device__ __align__(16) unsigned g_wot[NLAYERS * DM * DM];
__device__ __align__(16) unsigned g_wl1t[NLAYERS * DM * DFFN];
__device__ __align__(16) unsigned g_wl2t[NLAYERS * DFFN * DM];

// ---------------- helpers ----------------
__device__ __forceinline__ unsigned tf32_of(float v) {
    unsigned r;
    asm("cvt.rna.tf32.f32 %0, %1;" : "=r"(r) : "f"(v));
    return r;
}
__device__ __forceinline__ void cpa16(unsigned saddr, const void* g) {
    asm volatile("cp.async.cg.shared.global [%0], [%1], 16;" :: "r"(saddr), "l"(g));
}
__device__ __forceinline__ void ldsm4(unsigned& r0, unsigned& r1, unsigned& r2, unsigned& r3,
                                      unsigned addr) {
    asm volatile("ldmatrix.sync.aligned.m8n8.x4.shared.b16 {%0,%1,%2,%3}, [%4];"
                 : "=r"(r0), "=r"(r1), "=r"(r2), "=r"(r3) : "r"(addr));
}

// ---------------- weight convert + transpose: W[K][N] -> Wt[N][K] (tf32 bits) ----------------
__global__ void cvtw_t_kernel(const float* __restrict__ W, unsigned* __restrict__ Wt,
                              int K, int N) {
    __shared__ unsigned tile[32][33];
    size_t lo = (size_t)blockIdx.z * K * N;
    int k0 = blockIdx.y * 32, n0 = blockIdx.x * 32;
    int tx = threadIdx.x, ty = threadIdx.y;   // 32 x 8
#pragma unroll
    for (int i = ty; i < 32; i += 8)
        tile[i][tx] = tf32_of(W[lo + (size_t)(k0 + i) * N + n0 + tx]);
    __syncthreads();
#pragma unroll
    for (int i = ty; i < 32; i += 8)
        Wt[lo + (size_t)(n0 + i) * K + k0 + tx] = tile[tx][i];
}

// ---------------- init: x, tf32(x), tf32(x+pos) ----------------
__global__ void init_kernel(const float* __restrict__ src, const float* __restrict__ pos,
                            float* __restrict__ x, unsigned* __restrict__ xt,
                            unsigned* __restrict__ qt, int n) {
    int i = blockIdx.x * blockDim.x + threadIdx.x;
    if (i >= n) return;
    float s = src[i];
    x[i] = s;
    xt[i] = tf32_of(s);
    qt[i] = tf32_of(s + pos[i]);
}

// ---------------- reference points ----------------
__global__ void refpts_kernel(const float* __restrict__ vr, float* __restrict__ ref) {
    int idx = blockIdx.x * blockDim.x + threadIdx.x;
    if (idx >= MROWS) return;
    int n = idx / LEN, t = idx % LEN;
    int lvl = 3;
    if (t < 4096) lvl = 0; else if (t < 5120) lvl = 1; else if (t < 5376) lvl = 2;
    int s = c_S[lvl], hw = c_HW[lvl];
    int local = t - s;
    int i = local / hw, j = local % hw;
    float ry = (i + 0.5f) / (vr[(n * 4 + lvl) * 2 + 1] * (float)hw);
    float rx = (j + 0.5f) / (vr[(n * 4 + lvl) * 2 + 0] * (float)hw);
#pragma unroll
    for (int l2 = 0; l2 < 4; l2++) {
        ref[idx * 8 + l2 * 2 + 0] = rx * vr[(n * 4 + l2) * 2 + 0];
        ref[idx * 8 + l2 * 2 + 1] = ry * vr[(n * 4 + l2) * 2 + 1];
    }
}

// ---------------- tensor-core GEMM: tf32 mma.sync + cp.async + ldmatrix ----------------
// A [M][K] tf32 bits row-major; Wt [Nc][K] tf32 bits (transposed weight).
// Smem: XOR swizzle — word (row, k) lives at row*32 + ((k>>2) ^ (row&7))*4 + (k&3).
template <bool RELU_CVT>
__global__ void __launch_bounds__(256, 3) gemm_tc(
    const unsigned* __restrict__ A, const unsigned* __restrict__ Wt,
    const float* __restrict__ bias, float* __restrict__ C, int K, int Nc)
{
    extern __shared__ unsigned sm[];
    unsigned sbase = (unsigned)__cvta_generic_to_shared(sm);

    int tid  = threadIdx.x;
    int lane = tid & 31;
    int warp = tid >> 5;
    int wm = warp >> 1;       // 0..3
    int wn = warp & 1;        // 0..1
    int gid = lane >> 2;      // 0..7
    int tq  = lane & 3;       // 0..3

    int rowBase = blockIdx.y * BM;
    int colBase = blockIdx.x * BN;

    // ---- global->shared producer mapping ----
    int ar = tid >> 3;            // 0..31 (4 iters of +32)
    int ach = tid & 7;            // A chunk 0..7
    int br = tid >> 2;            // 0..63
    int bch = tid & 3;            // B chunk 0..3 (+4 on 2nd iter)

    const unsigned* Ag = A  + (size_t)(rowBase + ar) * K + ach * 4;
    const unsigned* Wg = Wt + (size_t)(colBase + br) * K + bch * 4;

    unsigned aswc = (unsigned)((ach ^ (ar & 7)) * 16);
    unsigned adst0 = sbase + (unsigned)(ar * 128) + aswc;
    unsigned bdst0 = sbase + (unsigned)(NSTAGE * ASTRIDE * 4) + (unsigned)(br * 128);

    auto issue = [&](int s, int k0) {
        unsigned ad = adst0 + (unsigned)(s * ASTRIDE * 4);
#pragma unroll
        for (int i = 0; i < 4; i++)
            cpa16(ad + (unsigned)(i * 32 * 128), Ag + (size_t)(32 * i) * K + k0);
        unsigned bd = bdst0 + (unsigned)(s * BSTRIDE * 4);
#pragma unroll
        for (int i = 0; i < 2; i++) {
            unsigned c = bch + 4 * i;
            cpa16(bd + (unsigned)((c ^ (br & 7)) * 16), Wg + (size_t)(k0 + 16 * i));
        }
        asm volatile("cp.async.commit_group;");
    };

    // ---- ldmatrix consumer addressing ----
    int rloc = lane & 15;             // row within 16-row matrix pair
    int hv   = lane >> 4;             // chunk half select
    int l7   = lane & 7;
    unsigned rowA[2], rowB[2];
#pragma unroll
    for (int mt = 0; mt < 2; mt++)
        rowA[mt] = sbase + (unsigned)((wm * 32 + mt * 16 + rloc) * 128);
    unsigned bregion = sbase + (unsigned)(NSTAGE * ASTRIDE * 4);
#pragma unroll
    for (int p = 0; p < 2; p++)
        rowB[p] = bregion + (unsigned)((wn * 32 + p * 16 + rloc) * 128);

    float c[2][4][4];
#pragma unroll
    for (int i = 0; i < 2; i++)
#pragma unroll
        for (int j = 0; j < 4; j++)
#pragma unroll
            for (int r = 0; r < 4; r++) c[i][j][r] = 0.f;

    int T = K / BK;
    issue(0, 0);
    issue(1, BK);

    for (int t = 0; t < T; t++) {
        asm volatile("cp.async.wait_group 1;");
        __syncthreads();
        if (t + 2 < T) issue((t + 2) % NSTAGE, (t + 2) * BK);
        else asm volatile("cp.async.commit_group;");

        unsigned aoff = (unsigned)((t % NSTAGE) * ASTRIDE * 4);
        unsigned boff = (unsigned)((t % NSTAGE) * BSTRIDE * 4);

#pragma unroll
        for (int ks = 0; ks < 4; ks++) {
            unsigned swc = (unsigned)((((2 * ks + hv) ^ l7)) * 16);
            unsigned aa[2][4], bb[2][4];
#pragma unroll
            for (int mt = 0; mt < 2; mt++)
                ldsm4(aa[mt][0], aa[mt][1], aa[mt][2], aa[mt][3], rowA[mt] + aoff + swc);
#pragma unroll
            for (int p = 0; p < 2; p++)
                ldsm4(bb[p][0], bb[p][1], bb[p][2], bb[p][3], rowB[p] + boff + swc);
#pragma unroll
            for (int p = 0; p < 2; p++) {
#pragma unroll
                for (int q = 0; q < 2; q++) {
                    int nt = 2 * p + q;
                    unsigned b0 = bb[p][q], b1 = bb[p][q + 2];
#pragma unroll
                    for (int mt = 0; mt < 2; mt++) {
                        asm volatile(
                            "mma.sync.aligned.m16n8k8.row.col.f32.tf32.tf32.f32 "
                            "{%0,%1,%2,%3}, {%4,%5,%6,%7}, {%8,%9}, {%0,%1,%2,%3};\n"
                            : "+f"(c[mt][nt][0]), "+f"(c[mt][nt][1]),
                              "+f"(c[mt][nt][2]), "+f"(c[mt][nt][3])
                            : "r"(aa[mt][0]), "r"(aa[mt][1]), "r"(aa[mt][2]), "r"(aa[mt][3]),
                              "r"(b0), "r"(b1));
                    }
                }
            }
        }
        __syncthreads();
    }

    // epilogue
#pragma unroll
    for (int mt = 0; mt < 2; mt++) {
#pragma unroll
        for (int nt = 0; nt < 4; nt++) {
            int r0 = rowBase + wm * 32 + mt * 16 + gid;
            int cc = colBase + wn * 32 + nt * 8 + tq * 2;
            float b0v = bias[cc], b1v = bias[cc + 1];
            float v0 = c[mt][nt][0] + b0v, v1 = c[mt][nt][1] + b1v;
            float v2 = c[mt][nt][2] + b0v, v3 = c[mt][nt][3] + b1v;
            if (RELU_CVT) {
                uint2 p0, p1;
                p0.x = tf32_of(fmaxf(v0, 0.f)); p0.y = tf32_of(fmaxf(v1, 0.f));
                p1.x = tf32_of(fmaxf(v2, 0.f)); p1.y = tf32_of(fmaxf(v3, 0.f));
                *(uint2*)((unsigned*)C + (size_t)r0 * Nc + cc)       = p0;
                *(uint2*)((unsigned*)C + (size_t)(r0 + 8) * Nc + cc) = p1;
            } else {
                *(float2*)(C + (size_t)r0 * Nc + cc)       = make_float2(v0, v1);
                *(float2*)(C + (size_t)(r0 + 8) * Nc + cc) = make_float2(v2, v3);
            }
        }
    }
}

// ---------------- deformable bilinear sampling (softmax fused, writes tf32) ----------------
__global__ void __launch_bounds__(256) sample_kernel(
    const float* __restrict__ value, const float* __restrict__ off,
    const float* __restrict__ aw, const float* __restrict__ ref,
    unsigned* __restrict__ attnt)
{
    int row = blockIdx.x;
    int h = threadIdx.x >> 5;
    int lane = threadIdx.x & 31;
    int n = row / LEN;

    float offv = off[(size_t)row * 256 + h * 32 + lane];
    float awraw = (lane < 16) ? aw[(size_t)row * 128 + h * 16 + lane] : -1e30f;
    float refv = (lane < 8)  ? ref[(size_t)row * 8 + lane] : 0.f;

    // softmax over 16 lanes (fused)
    float mx = awraw;
#pragma unroll
    for (int o = 8; o; o >>= 1) mx = fmaxf(mx, __shfl_xor_sync(0xffffffffu, mx, o, 16));
    float e = (lane < 16) ? expf(awraw - mx) : 0.f;
    float ssum = e;
#pragma unroll
    for (int o = 8; o; o >>= 1) ssum += __shfl_xor_sync(0xffffffffu, ssum, o, 16);
    float awv = e / ssum;

    const float* vbase = value + (size_t)n * LEN * 256 + h * 32 + lane;
    float acc = 0.f;
#pragma unroll
    for (int p = 0; p < 16; p++) {
        int lvl = p >> 2;
        float ox = __shfl_sync(0xffffffffu, offv, 2 * p);
        float oy = __shfl_sync(0xffffffffu, offv, 2 * p + 1);
        float a  = __shfl_sync(0xffffffffu, awv, p);
        float rx = __shfl_sync(0xffffffffu, refv, 2 * lvl);
        float ry = __shfl_sync(0xffffffffu, refv, 2 * lvl + 1);
        int HW = c_HW[lvl], s = c_S[lvl];
        float fw = (float)HW;
        float xf = (rx + ox / fw) * fw - 0.5f;
        float yf = (ry + oy / fw) * fw - 0.5f;
        float x0f = floorf(xf), y0f = floorf(yf);
        int ix = (int)x0f, iy = (int)y0f;
        float wx1 = xf - x0f, wy1 = yf - y0f;
        float wx0 = 1.f - wx1, wy0 = 1.f - wy1;
        const float* vb = vbase + (size_t)s * 256;
        bool xin0 = (ix >= 0) && (ix < HW);
        bool xin1 = (ix + 1 >= 0) && (ix + 1 < HW);
        bool yin0 = (iy >= 0) && (iy < HW);
        bool yin1 = (iy + 1 >= 0) && (iy + 1 < HW);
        float smp = 0.f;
        if (xin0 && yin0) smp += wx0 * wy0 * vb[(size_t)(iy * HW + ix) * 256];
        if (xin1 && yin0) smp += wx1 * wy0 * vb[(size_t)(iy * HW + ix + 1) * 256];
        if (xin0 && yin1) smp += wx0 * wy1 * vb[(size_t)((iy + 1) * HW + ix) * 256];
        if (xin1 && yin1) smp += wx1 * wy1 * vb[(size_t)((iy + 1) * HW + ix + 1) * 256];
        acc += a * smp;
    }
    attnt[(size_t)row * 256 + h * 32 + lane] = tf32_of(acc);
}

// ---------------- residual add + LayerNorm (+optional tf32 aux outputs) ----------------
template <bool AUX>
__global__ void __launch_bounds__(256) add_ln_kernel(
    const float* __restrict__ x, const float* __restrict__ dlt,
    const float* __restrict__ g, const float* __restrict__ be,
    const float* __restrict__ pos,
    float* __restrict__ out, unsigned* __restrict__ xt, unsigned* __restrict__ qt)
{
    __shared__ float sh[8];
    __shared__ float bcast;
    int row = blockIdx.x, tid = threadIdx.x;
    float v = x[(size_t)row * DM + tid] + dlt[(size_t)row * DM + tid];

    float s = v;
#pragma unroll
    for (int o = 16; o; o >>= 1) s += __shfl_down_sync(0xffffffffu, s, o);
    if ((tid & 31) == 0) sh[tid >> 5] = s;
    __syncthreads();
    if (tid < 8) {
        float t2 = sh[tid];
#pragma unroll
        for (int o = 4; o; o >>= 1) t2 += __shfl_down_sync(0xffu, t2, o);
        if (tid == 0) bcast = t2;
    }
    __syncthreads();
    float mean = bcast * (1.0f / DM);
    float d = v - mean;

    __syncthreads();
    float s2 = d * d;
#pragma unroll
    for (int o = 16; o; o >>= 1) s2 += __shfl_down_sync(0xffffffffu, s2, o);
    if ((tid & 31) == 0) sh[tid >> 5] = s2;
    __syncthreads();
    if (tid < 8) {
        float t2 = sh[tid];
#pragma unroll
        for (int o = 4; o; o >>= 1) t2 += __shfl_down_sync(0xffu, t2, o);
        if (tid == 0) bcast = t2;
    }
    __syncthreads();
    float var = bcast * (1.0f / DM);
    float r = d * rsqrtf(var + 1e-5f) * g[tid] + be[tid];
    out[(size_t)row * DM + tid] = r;
    if (AUX) {
        xt[(size_t)row * DM + tid] = tf32_of(r);
        qt[(size_t)row * DM + tid] = tf32_of(r + pos[(size_t)row * DM + tid]);
    }
}

// ---------------- launch ----------------
extern "C" void kernel_launch(void* const* d_in, const int* in_sizes, int n_in,
                              void* d_out, int out_size)
{
    (void)in_sizes; (void)n_in; (void)out_size;
    const float* src  = (const float*)d_in[0];
    const float* pos  = (const float*)d_in[1];
    const float* vr   = (const float*)d_in[2];
    const float* Wv   = (const float*)d_in[3];
    const float* bv   = (const float*)d_in[4];
    const float* Woff = (const float*)d_in[5];
    const float* boff = (const float*)d_in[6];
    const float* Wa   = (const float*)d_in[7];
    const float* ba   = (const float*)d_in[8];
    const float* Wo   = (const float*)d_in[9];
    const float* bo   = (const float*)d_in[10];
    const float* g1   = (const float*)d_in[11];
    const float* be1  = (const float*)d_in[12];
    const float* Wl1  = (const float*)d_in[13];
    const float* bl1  = (const float*)d_in[14];
    const float* Wl2  = (const float*)d_in[15];
    const float* bl2  = (const float*)d_in[16];
    const float* g2   = (const float*)d_in[17];
    const float* be2  = (const float*)d_in[18];
    float* out = (float*)d_out;

    float *x, *val, *off, *aw, *tmp, *ref;
    unsigned *xt, *qt, *attnt, *ffnt;
    unsigned *wvt, *wofft, *wat, *wot, *wl1t, *wl2t;
    cudaGetSymbolAddress((void**)&x,     g_x);
    cudaGetSymbolAddress((void**)&xt,    g_xt);
    cudaGetSymbolAddress((void**)&qt,    g_qt);
    cudaGetSymbolAddress((void**)&val,   g_val);
    cudaGetSymbolAddress((void**)&off,   g_off);
    cudaGetSymbolAddress((void**)&aw,    g_aw);
    cudaGetSymbolAddress((void**)&attnt, g_attnt);
    cudaGetSymbolAddress((void**)&tmp,   g_tmp);
    cudaGetSymbolAddress((void**)&ffnt,  g_ffnt);
    cudaGetSymbolAddress((void**)&ref,   g_ref);
    cudaGetSymbolAddress((void**)&wvt,   g_wvt);
    cudaGetSymbolAddress((void**)&wofft, g_wofft);
    cudaGetSymbolAddress((void**)&wat,   g_wat);
    cudaGetSymbolAddress((void**)&wot,   g_wot);
    cudaGetSymbolAddress((void**)&wl1t,  g_wl1t);
    cudaGetSymbolAddress((void**)&wl2t,  g_wl2t);

    cudaFuncSetAttribute(gemm_tc<false>, cudaFuncAttributeMaxDynamicSharedMemorySize, SMEM_BYTES);
    cudaFuncSetAttribute(gemm_tc<true>,  cudaFuncAttributeMaxDynamicSharedMemorySize, SMEM_BYTES);

    // weight convert + transpose (per launch; cheap)
    dim3 tb(32, 8);
    cvtw_t_kernel<<<dim3(DM / 32, DM / 32, NLAYERS), tb>>>(Wv,   wvt,   DM, DM);
    cvtw_t_kernel<<<dim3(DM / 32, DM / 32, NLAYERS), tb>>>(Woff, wofft, DM, DM);
    cvtw_t_kernel<<<dim3(128 / 32, DM / 32, NLAYERS), tb>>>(Wa,  wat,   DM, 128);
    cvtw_t_kernel<<<dim3(DM / 32, DM / 32, NLAYERS), tb>>>(Wo,   wot,   DM, DM);
    cvtw_t_kernel<<<dim3(DFFN / 32, DM / 32, NLAYERS), tb>>>(Wl1, wl1t, DM, DFFN);
    cvtw_t_kernel<<<dim3(DM / 32, DFFN / 32, NLAYERS), tb>>>(Wl2, wl2t, DFFN, DM);

    int n = MROWS * DM;
    init_kernel<<<(n + 255) / 256, 256>>>(src, pos, x, xt, qt, n);
    refpts_kernel<<<(MROWS + 255) / 256, 256>>>(vr, ref);

    dim3 gDM(DM / BN, MROWS / BM);     // (4, 85)
    dim3 gAW(128 / BN, MROWS / BM);    // (2, 85)
    dim3 gFF(DFFN / BN, MROWS / BM);   // (16, 85)

    for (int l = 0; l < NLAYERS; l++) {
        gemm_tc<false><<<gDM, 256, SMEM_BYTES>>>(xt, wvt + (size_t)l * DM * DM,
            bv + l * DM, val, DM, DM);
        gemm_tc<false><<<gDM, 256, SMEM_BYTES>>>(qt, wofft + (size_t)l * DM * DM,
            boff + l * 256, off, DM, 256);
        gemm_tc<false><<<gAW, 256, SMEM_BYTES>>>(qt, wat + (size_t)l * DM * 128,
            ba + l * 128, aw, DM, 128);
        sample_kernel<<<MROWS, 256>>>(val, off, aw, ref, attnt);
        gemm_tc<false><<<gDM, 256, SMEM_BYTES>>>(attnt, wot + (size_t)l * DM * DM,
            bo + l * DM, tmp, DM, DM);
        add_ln_kernel<true><<<MROWS, 256>>>(x, tmp, g1 + l * DM, be1 + l * DM, pos, x, xt, qt);
        gemm_tc<true ><<<gFF, 256, SMEM_BYTES>>>(xt, wl1t + (size_t)l * DM * DFFN,
            bl1 + l * DFFN, (float*)ffnt, DM, DFFN);
        gemm_tc<false><<<gDM, 256, SMEM_BYTES>>>(ffnt, wl2t + (size_t)l * DFFN * DM,
            bl2 + l * DM, tmp, DFFN, DM);
        if (l == NLAYERS - 1)
            add_ln_kernel<false><<<MROWS, 256>>>(x, tmp, g2 + l * DM, be2 + l * DM, pos, out, xt, qt);
        else
            add_ln_kernel<true ><<<MROWS, 256>>>(x, tmp, g2 + l * DM, be2 + l * DM, pos, x, xt, qt);
    }
}

// round 5
// speedup vs baseline: 2.8939x; 1.3332x over previous
#include <cuda_runtime.h>
#include <cuda_fp16.h>
#include <math.h>

#define LEN 5440
#define NBATCH 2
#define MROWS (NBATCH*LEN)   /* 10880 */
#define DM 256
#define NH 8
#define DFFN 1024
#define NLAYERS 2
#define NQ 384               /* fused off|aw output width */

// fp16 tensor-core GEMM tile
#define BM 128
#define BN 64
#define BK 64                 /* halves per k-tile = 128B rows */
#define NSTAGE 3
#define ABYTES (BM*128)       /* 16384 per stage */
#define BBYTES (BN*128)       /* 8192 per stage */
#define SMEM_BYTES (NSTAGE*(ABYTES+BBYTES))   /* 73728 */

__constant__ int c_HW[4] = {64, 32, 16, 8};
__constant__ int c_S[4]  = {0, 4096, 5120, 5376};

// ---------------- scratch ----------------
__device__ __align__(16) float  g_x[MROWS * DM];
__device__ __align__(16) __half g_xh[MROWS * DM];
__device__ __align__(16) __half g_qh[MROWS * DM];
__device__ __align__(16) __half g_valh[MROWS * DM];
__device__ __align__(16) float  g_offaw[MROWS * NQ];
__device__ __align__(16) __half g_attnh[MROWS * DM];
__device__ __align__(16) float  g_tmp[MROWS * DM];
__device__ __align__(16) __half g_ffnh[MROWS * DFFN];
__device__ __align__(16) float  g_ref[MROWS * 8];
// converted + transposed fp16 weights: [N][K], k-contiguous
__device__ __align__(16) __half g_wvh[NLAYERS * DM * DM];
__device__ __align__(16) __half g_wqh[NLAYERS * NQ * DM];
__device__ __align__(16) __half g_woh[NLAYERS * DM * DM];
__device__ __align__(16) __half g_wl1h[NLAYERS * DM * DFFN];
__device__ __align__(16) __half g_wl2h[NLAYERS * DFFN * DM];
__device__ __align__(16) float  g_bq[NLAYERS * NQ];

// ---------------- helpers ----------------
__device__ __forceinline__ void cpa16(unsigned saddr, const void* g) {
    asm volatile("cp.async.cg.shared.global [%0], [%1], 16;" :: "r"(saddr), "l"(g));
}
__device__ __forceinline__ void ldsm4(unsigned& r0, unsigned& r1, unsigned& r2, unsigned& r3,
                                      unsigned addr) {
    asm volatile("ldmatrix.sync.aligned.m8n8.x4.shared.b16 {%0,%1,%2,%3}, [%4];"
                 : "=r"(r0), "=r"(r1), "=r"(r2), "=r"(r3) : "r"(addr));
}

// ---------------- one-shot weight convert + transpose + bias concat ----------------
// grid.x = NLAYERS*737, block (32,8)
__global__ void cvt_all_kernel(
    const float* __restrict__ Wv, const float* __restrict__ Woff, const float* __restrict__ Wa,
    const float* __restrict__ Wo, const float* __restrict__ Wl1, const float* __restrict__ Wl2,
    const float* __restrict__ boff, const float* __restrict__ ba,
    __half* __restrict__ wvh, __half* __restrict__ wqh, __half* __restrict__ woh,
    __half* __restrict__ wl1h, __half* __restrict__ wl2h, float* __restrict__ bq)
{
    __shared__ float tile[32][33];
    int bx = blockIdx.x;
    int l = bx / 737, r = bx % 737;
    int tx = threadIdx.x, ty = threadIdx.y;
    if (r == 736) {
        int t = ty * 32 + tx;
        for (int i = t; i < NQ; i += 256)
            bq[l * NQ + i] = (i < 256) ? boff[l * 256 + i] : ba[l * 128 + i - 256];
        return;
    }
    const float* src; __half* dst; int K, N, t, rowOff = 0;
    if (r < 64)       { src = Wv   + (size_t)l * 256 * 256;  dst = wvh  + (size_t)l * 256 * 256;  K = 256;  N = 256;  t = r; }
    else if (r < 128) { src = Woff + (size_t)l * 256 * 256;  dst = wqh  + (size_t)l * NQ * 256;   K = 256;  N = 256;  t = r - 64; }
    else if (r < 160) { src = Wa   + (size_t)l * 256 * 128;  dst = wqh  + (size_t)l * NQ * 256;   K = 256;  N = 128;  t = r - 128; rowOff = 256; }
    else if (r < 224) { src = Wo   + (size_t)l * 256 * 256;  dst = woh  + (size_t)l * 256 * 256;  K = 256;  N = 256;  t = r - 160; }
    else if (r < 480) { src = Wl1  + (size_t)l * 256 * 1024; dst = wl1h + (size_t)l * 256 * 1024; K = 256;  N = 1024; t = r - 224; }
    else              { src = Wl2  + (size_t)l * 1024 * 256; dst = wl2h + (size_t)l * 1024 * 256; K = 1024; N = 256;  t = r - 480; }
    int tn = t % (N / 32), tk = t / (N / 32);
    int k0 = tk * 32, n0 = tn * 32;
#pragma unroll
    for (int i = ty; i < 32; i += 8)
        tile[i][tx] = src[(size_t)(k0 + i) * N + n0 + tx];
    __syncthreads();
#pragma unroll
    for (int i = ty; i < 32; i += 8)
        dst[(size_t)(rowOff + n0 + i) * K + k0 + tx] = __float2half_rn(tile[tx][i]);
}

// ---------------- init: x, fp16(x), fp16(x+pos) ----------------
__global__ void init_kernel(const float* __restrict__ src, const float* __restrict__ pos,
                            float* __restrict__ x, __half* __restrict__ xh,
                            __half* __restrict__ qh, int n) {
    int i = blockIdx.x * blockDim.x + threadIdx.x;
    if (i >= n) return;
    float s = src[i];
    x[i] = s;
    xh[i] = __float2half_rn(s);
    qh[i] = __float2half_rn(s + pos[i]);
}

// ---------------- reference points ----------------
__global__ void refpts_kernel(const float* __restrict__ vr, float* __restrict__ ref) {
    int idx = blockIdx.x * blockDim.x + threadIdx.x;
    if (idx >= MROWS) return;
    int n = idx / LEN, t = idx % LEN;
    int lvl = 3;
    if (t < 4096) lvl = 0; else if (t < 5120) lvl = 1; else if (t < 5376) lvl = 2;
    int s = c_S[lvl], hw = c_HW[lvl];
    int local = t - s;
    int i = local / hw, j = local % hw;
    float ry = (i + 0.5f) / (vr[(n * 4 + lvl) * 2 + 1] * (float)hw);
    float rx = (j + 0.5f) / (vr[(n * 4 + lvl) * 2 + 0] * (float)hw);
#pragma unroll
    for (int l2 = 0; l2 < 4; l2++) {
        ref[idx * 8 + l2 * 2 + 0] = rx * vr[(n * 4 + l2) * 2 + 0];
        ref[idx * 8 + l2 * 2 + 1] = ry * vr[(n * 4 + l2) * 2 + 1];
    }
}

// ---------------- fp16 tensor-core GEMM: mma.m16n8k16 + cp.async + ldmatrix ----------------
// A [M][K] fp16 row-major; Wt [Nc][K] fp16 (transposed weight, k-contiguous).
// Smem 128B rows, XOR swizzle: chunk c of row r -> (c ^ (r&7)).
// OUTMODE: 0 = fp32, 1 = fp16, 2 = relu->fp16.
template <int OUTMODE>
__global__ void __launch_bounds__(256, 3) gemm_tc(
    const __half* __restrict__ A, const __half* __restrict__ Wt,
    const float* __restrict__ bias, void* __restrict__ Cv, int K, int Nc)
{
    extern __shared__ char smc[];
    unsigned sbase = (unsigned)__cvta_generic_to_shared(smc);

    int tid  = threadIdx.x;
    int lane = tid & 31;
    int warp = tid >> 5;
    int wm = warp >> 1, wn = warp & 1;
    int gid = lane >> 2, tq = lane & 3;
    int l7 = lane & 7;

    int rowBase = blockIdx.y * BM;
    int colBase = blockIdx.x * BN;

    // producers: 16B per thread
    int ar = tid >> 3, ach = tid & 7;        // A: 128 rows x 8 chunks, 4 iters
    int br = tid >> 2, bch = tid & 3;        // B: 64 rows x 8 chunks, 2 iters

    const __half* Ag = A  + (size_t)(rowBase + ar) * K + ach * 8;
    const __half* Wg = Wt + (size_t)(colBase + br) * K + bch * 8;

    unsigned adst0 = sbase + (unsigned)(ar * 128) + (unsigned)((ach ^ (ar & 7)) * 16);
    unsigned bdst0 = sbase + (unsigned)(NSTAGE * ABYTES) + (unsigned)(br * 128);

    auto issue = [&](int s, int k0) {
        unsigned ad = adst0 + (unsigned)(s * ABYTES);
#pragma unroll
        for (int i = 0; i < 4; i++)
            cpa16(ad + (unsigned)(i * 32 * 128), Ag + (size_t)(32 * i) * K + k0);
        unsigned bd = bdst0 + (unsigned)(s * BBYTES);
#pragma unroll
        for (int i = 0; i < 2; i++) {
            unsigned c = bch + 4 * i;
            cpa16(bd + (unsigned)((c ^ (br & 7)) * 16), Wg + (size_t)(k0 + 32 * i));
        }
        asm volatile("cp.async.commit_group;");
    };

    // consumer ldmatrix addressing
    int rlocA = lane & 15, hvA = lane >> 4;
    unsigned rowA[2];
#pragma unroll
    for (int mt = 0; mt < 2; mt++)
        rowA[mt] = sbase + (unsigned)((wm * 32 + mt * 16 + rlocA) * 128);
    int nrow = ((lane >> 4) & 1) * 8 + l7;   // 0..15 within 16-row group
    int hvB = (lane >> 3) & 1;
    unsigned bregion = sbase + (unsigned)(NSTAGE * ABYTES);
    unsigned rowB[2];
#pragma unroll
    for (int p = 0; p < 2; p++)
        rowB[p] = bregion + (unsigned)((wn * 32 + p * 16 + nrow) * 128);

    float c[2][4][4];
#pragma unroll
    for (int i = 0; i < 2; i++)
#pragma unroll
        for (int j = 0; j < 4; j++)
#pragma unroll
            for (int r = 0; r < 4; r++) c[i][j][r] = 0.f;

    int T = K / BK;
    issue(0, 0);
    issue(1, BK);

    for (int t = 0; t < T; t++) {
        asm volatile("cp.async.wait_group 1;");
        __syncthreads();
        if (t + 2 < T) issue((t + 2) % NSTAGE, (t + 2) * BK);
        else asm volatile("cp.async.commit_group;");

        unsigned aoff = (unsigned)((t % NSTAGE) * ABYTES);
        unsigned boff = (unsigned)((t % NSTAGE) * BBYTES);

#pragma unroll
        for (int ks = 0; ks < 4; ks++) {
            unsigned swcA = (unsigned)(((2 * ks + hvA) ^ l7) * 16);
            unsigned swcB = (unsigned)(((2 * ks + hvB) ^ l7) * 16);
            unsigned aa[2][4], bb[2][4];
#pragma unroll
            for (int mt = 0; mt < 2; mt++)
                ldsm4(aa[mt][0], aa[mt][1], aa[mt][2], aa[mt][3], rowA[mt] + aoff + swcA);
#pragma unroll
            for (int p = 0; p < 2; p++)
                ldsm4(bb[p][0], bb[p][1], bb[p][2], bb[p][3], rowB[p] + boff + swcB);
#pragma unroll
            for (int p = 0; p < 2; p++) {
#pragma unroll
                for (int q = 0; q < 2; q++) {
                    int nt = 2 * p + q;
                    unsigned b0 = bb[p][2 * q], b1 = bb[p][2 * q + 1];
#pragma unroll
                    for (int mt = 0; mt < 2; mt++) {
                        asm volatile(
                            "mma.sync.aligned.m16n8k16.row.col.f32.f16.f16.f32 "
                            "{%0,%1,%2,%3}, {%4,%5,%6,%7}, {%8,%9}, {%0,%1,%2,%3};\n"
                            : "+f"(c[mt][nt][0]), "+f"(c[mt][nt][1]),
                              "+f"(c[mt][nt][2]), "+f"(c[mt][nt][3])
                            : "r"(aa[mt][0]), "r"(aa[mt][1]), "r"(aa[mt][2]), "r"(aa[mt][3]),
                              "r"(b0), "r"(b1));
                    }
                }
            }
        }
        __syncthreads();
    }

    // epilogue
#pragma unroll
    for (int mt = 0; mt < 2; mt++) {
#pragma unroll
        for (int nt = 0; nt < 4; nt++) {
            int r0 = rowBase + wm * 32 + mt * 16 + gid;
            int cc = colBase + wn * 32 + nt * 8 + tq * 2;
            float b0v = bias[cc], b1v = bias[cc + 1];
            float v0 = c[mt][nt][0] + b0v, v1 = c[mt][nt][1] + b1v;
            float v2 = c[mt][nt][2] + b0v, v3 = c[mt][nt][3] + b1v;
            if (OUTMODE == 0) {
                float* C = (float*)Cv;
                *(float2*)(C + (size_t)r0 * Nc + cc)       = make_float2(v0, v1);
                *(float2*)(C + (size_t)(r0 + 8) * Nc + cc) = make_float2(v2, v3);
            } else {
                if (OUTMODE == 2) {
                    v0 = fmaxf(v0, 0.f); v1 = fmaxf(v1, 0.f);
                    v2 = fmaxf(v2, 0.f); v3 = fmaxf(v3, 0.f);
                }
                __half* C = (__half*)Cv;
                *(__half2*)(C + (size_t)r0 * Nc + cc)       = __floats2half2_rn(v0, v1);
                *(__half2*)(C + (size_t)(r0 + 8) * Nc + cc) = __floats2half2_rn(v2, v3);
            }
        }
    }
}

// ---------------- deformable sampling: fused softmax, fp16 value ----------------
__global__ void __launch_bounds__(256) sample_kernel(
    const __half* __restrict__ value, const float* __restrict__ offaw,
    const float* __restrict__ ref, __half* __restrict__ attnh)
{
    int row = blockIdx.x;
    int h = threadIdx.x >> 5;
    int lane = threadIdx.x & 31;
    int n = row / LEN;

    float offv = offaw[(size_t)row * NQ + h * 32 + lane];
    float awraw = (lane < 16) ? offaw[(size_t)row * NQ + 256 + h * 16 + lane] : -1e30f;
    float refv = (lane < 8)  ? ref[(size_t)row * 8 + lane] : 0.f;

    float mx = awraw;
#pragma unroll
    for (int o = 8; o; o >>= 1) mx = fmaxf(mx, __shfl_xor_sync(0xffffffffu, mx, o, 16));
    float e = (lane < 16) ? expf(awraw - mx) : 0.f;
    float ssum = e;
#pragma unroll
    for (int o = 8; o; o >>= 1) ssum += __shfl_xor_sync(0xffffffffu, ssum, o, 16);
    float awv = e / ssum;

    const __half* vbase = value + (size_t)n * LEN * 256 + h * 32 + lane;
    float acc = 0.f;
#pragma unroll
    for (int p = 0; p < 16; p++) {
        int lvl = p >> 2;
        float ox = __shfl_sync(0xffffffffu, offv, 2 * p);
        float oy = __shfl_sync(0xffffffffu, offv, 2 * p + 1);
        float a  = __shfl_sync(0xffffffffu, awv, p);
        float rx = __shfl_sync(0xffffffffu, refv, 2 * lvl);
        float ry = __shfl_sync(0xffffffffu, refv, 2 * lvl + 1);
        int HW = c_HW[lvl], s = c_S[lvl];
        float fw = (float)HW;
        float xf = (rx + ox / fw) * fw - 0.5f;
        float yf = (ry + oy / fw) * fw - 0.5f;
        float x0f = floorf(xf), y0f = floorf(yf);
        int ix = (int)x0f, iy = (int)y0f;
        float wx1 = xf - x0f, wy1 = yf - y0f;
        float wx0 = 1.f - wx1, wy0 = 1.f - wy1;
        const __half* vb = vbase + (size_t)s * 256;
        bool xin0 = (ix >= 0) && (ix < HW);
        bool xin1 = (ix + 1 >= 0) && (ix + 1 < HW);
        bool yin0 = (iy >= 0) && (iy < HW);
        bool yin1 = (iy + 1 >= 0) && (iy + 1 < HW);
        float smp = 0.f;
        if (xin0 && yin0) smp += wx0 * wy0 * __half2float(vb[(size_t)(iy * HW + ix) * 256]);
        if (xin1 && yin0) smp += wx1 * wy0 * __half2float(vb[(size_t)(iy * HW + ix + 1) * 256]);
        if (xin0 && yin1) smp += wx0 * wy1 * __half2float(vb[(size_t)((iy + 1) * HW + ix) * 256]);
        if (xin1 && yin1) smp += wx1 * wy1 * __half2float(vb[(size_t)((iy + 1) * HW + ix + 1) * 256]);
        acc += a * smp;
    }
    attnh[(size_t)row * 256 + h * 32 + lane] = __float2half_rn(acc);
}

// ---------------- residual add + LayerNorm (+fp16 aux) ----------------
template <bool AUX>
__global__ void __launch_bounds__(256) add_ln_kernel(
    const float* __restrict__ x, const float* __restrict__ dlt,
    const float* __restrict__ g, const float* __restrict__ be,
    const float* __restrict__ pos,
    float* __restrict__ out, __half* __restrict__ xh, __half* __restrict__ qh)
{
    __shared__ float sh[8];
    __shared__ float bcast;
    int row = blockIdx.x, tid = threadIdx.x;
    float v = x[(size_t)row * DM + tid] + dlt[(size_t)row * DM + tid];

    float s = v;
#pragma unroll
    for (int o = 16; o; o >>= 1) s += __shfl_down_sync(0xffffffffu, s, o);
    if ((tid & 31) == 0) sh[tid >> 5] = s;
    __syncthreads();
    if (tid < 8) {
        float t2 = sh[tid];
#pragma unroll
        for (int o = 4; o; o >>= 1) t2 += __shfl_down_sync(0xffu, t2, o);
        if (tid == 0) bcast = t2;
    }
    __syncthreads();
    float mean = bcast * (1.0f / DM);
    float d = v - mean;

    __syncthreads();
    float s2 = d * d;
#pragma unroll
    for (int o = 16; o; o >>= 1) s2 += __shfl_down_sync(0xffffffffu, s2, o);
    if ((tid & 31) == 0) sh[tid >> 5] = s2;
    __syncthreads();
    if (tid < 8) {
        float t2 = sh[tid];
#pragma unroll
        for (int o = 4; o; o >>= 1) t2 += __shfl_down_sync(0xffu, t2, o);
        if (tid == 0) bcast = t2;
    }
    __syncthreads();
    float var = bcast * (1.0f / DM);
    float r = d * rsqrtf(var + 1e-5f) * g[tid] + be[tid];
    out[(size_t)row * DM + tid] = r;
    if (AUX) {
        xh[(size_t)row * DM + tid] = __float2half_rn(r);
        qh[(size_t)row * DM + tid] = __float2half_rn(r + pos[(size_t)row * DM + tid]);
    }
}

// ---------------- launch ----------------
extern "C" void kernel_launch(void* const* d_in, const int* in_sizes, int n_in,
                              void* d_out, int out_size)
{
    (void)in_sizes; (void)n_in; (void)out_size;
    const float* src  = (const float*)d_in[0];
    const float* pos  = (const float*)d_in[1];
    const float* vr   = (const float*)d_in[2];
    const float* Wv   = (const float*)d_in[3];
    const float* bv   = (const float*)d_in[4];
    const float* Woff = (const float*)d_in[5];
    const float* boff = (const float*)d_in[6];
    const float* Wa   = (const float*)d_in[7];
    const float* ba   = (const float*)d_in[8];
    const float* Wo   = (const float*)d_in[9];
    const float* bo   = (const float*)d_in[10];
    const float* g1   = (const float*)d_in[11];
    const float* be1  = (const float*)d_in[12];
    const float* Wl1  = (const float*)d_in[13];
    const float* bl1  = (const float*)d_in[14];
    const float* Wl2  = (const float*)d_in[15];
    const float* bl2  = (const float*)d_in[16];
    const float* g2   = (const float*)d_in[17];
    const float* be2  = (const float*)d_in[18];
    float* out = (float*)d_out;

    float *x, *offaw, *tmp, *ref, *bq;
    __half *xh, *qh, *valh, *attnh, *ffnh;
    __half *wvh, *wqh, *woh, *wl1h, *wl2h;
    cudaGetSymbolAddress((void**)&x,     g_x);
    cudaGetSymbolAddress((void**)&xh,    g_xh);
    cudaGetSymbolAddress((void**)&qh,    g_qh);
    cudaGetSymbolAddress((void**)&valh,  g_valh);
    cudaGetSymbolAddress((void**)&offaw, g_offaw);
    cudaGetSymbolAddress((void**)&attnh, g_attnh);
    cudaGetSymbolAddress((void**)&tmp,   g_tmp);
    cudaGetSymbolAddress((void**)&ffnh,  g_ffnh);
    cudaGetSymbolAddress((void**)&ref,   g_ref);
    cudaGetSymbolAddress((void**)&wvh,   g_wvh);
    cudaGetSymbolAddress((void**)&wqh,   g_wqh);
    cudaGetSymbolAddress((void**)&woh,   g_woh);
    cudaGetSymbolAddress((void**)&wl1h,  g_wl1h);
    cudaGetSymbolAddress((void**)&wl2h,  g_wl2h);
    cudaGetSymbolAddress((void**)&bq,    g_bq);

    cudaFuncSetAttribute(gemm_tc<0>, cudaFuncAttributeMaxDynamicSharedMemorySize, SMEM_BYTES);
    cudaFuncSetAttribute(gemm_tc<1>, cudaFuncAttributeMaxDynamicSharedMemorySize, SMEM_BYTES);
    cudaFuncSetAttribute(gemm_tc<2>, cudaFuncAttributeMaxDynamicSharedMemorySize, SMEM_BYTES);

    cvt_all_kernel<<<NLAYERS * 737, dim3(32, 8)>>>(Wv, Woff, Wa, Wo, Wl1, Wl2, boff, ba,
                                                   wvh, wqh, woh, wl1h, wl2h, bq);
    int n = MROWS * DM;
    init_kernel<<<(n + 255) / 256, 256>>>(src, pos, x, xh, qh, n);
    refpts_kernel<<<(MROWS + 255) / 256, 256>>>(vr, ref);

    dim3 gDM(DM / BN, MROWS / BM);     // (4, 85)
    dim3 gQ (NQ / BN, MROWS / BM);     // (6, 85)
    dim3 gFF(DFFN / BN, MROWS / BM);   // (16, 85)

    for (int l = 0; l < NLAYERS; l++) {
        gemm_tc<1><<<gDM, 256, SMEM_BYTES>>>(xh, wvh + (size_t)l * DM * DM,
            bv + l * DM, valh, DM, DM);
        gemm_tc<0><<<gQ, 256, SMEM_BYTES>>>(qh, wqh + (size_t)l * NQ * DM,
            bq + l * NQ, offaw, DM, NQ);
        sample_kernel<<<MROWS, 256>>>(valh, offaw, ref, attnh);
        gemm_tc<0><<<gDM, 256, SMEM_BYTES>>>(attnh, woh + (size_t)l * DM * DM,
            bo + l * DM, tmp, DM, DM);
        add_ln_kernel<true><<<MROWS, 256>>>(x, tmp, g1 + l * DM, be1 + l * DM, pos, x, xh, qh);
        gemm_tc<2><<<gFF, 256, SMEM_BYTES>>>(xh, wl1h + (size_t)l * DM * DFFN,
            bl1 + l * DFFN, ffnh, DM, DFFN);
        gemm_tc<0><<<gDM, 256, SMEM_BYTES>>>(ffnh, wl2h + (size_t)l * DFFN * DM,
            bl2 + l * DM, tmp, DFFN, DM);
        if (l == NLAYERS - 1)
            add_ln_kernel<false><<<MROWS, 256>>>(x, tmp, g2 + l * DM, be2 + l * DM, pos, out, xh, qh);
        else
            add_ln_kernel<true ><<<MROWS, 256>>>(x, tmp, g2 + l * DM, be2 + l * DM, pos, x, xh, qh);
    }
}